// round 2
// baseline (speedup 1.0000x reference)
#include <cuda_runtime.h>
#include <math.h>

#define B_    4096
#define FEW   5
#define NN_   64
#define D_    128
#define NSYM  100000
#define DM    256
#define DI    512
#define H_    512
#define G4    2048   // 4*H
#define KX    272    // padded K for step GEMM: 256 (h) + 5 (attn) + 11 pad

// ---------------- scratch (static device globals; no allocation) -------------
__device__ float  g_pe[(size_t)NSYM * 256];   // [sym][0:128]=pe_rel, [128:256]=pe_ent
__device__ float2 g_scal[NSYM];               // per-symbol score scalars (rel, ent)
__device__ float  g_Wcat[128 * 256];          // k-major fused gcn weight
__device__ float  g_u[2 * 128];               // folded attn vectors (rel, ent)
__device__ float  g_gw[2];                    // softmax(hop_gate)
__device__ float  g_biasvec[128];             // gcn_wb + gcn_b
__device__ float  g_qn[(size_t)B_ * DM];      // query_neighbor
__device__ float  g_sn[FEW * DM];             // support_neighbor
__device__ float  g_h1[FEW * DI];
__device__ float  g_z[FEW * DM];
__device__ float  g_sg[FEW * DM];             // support_g
__device__ float  g_sm[DM];                   // support mean
__device__ float  g_wihT[DM * G4];            // w_ih transposed  [256,2048]
__device__ float  g_Wstep[KX * G4];           // rows 0:256 = Whh_h^T, 256:261 = sgW, rest 0
__device__ float  g_bias2[G4];                // b_ih + b_hh
__device__ float  g_A[(size_t)B_ * G4];       // q @ w_ih.T + bias
__device__ float  g_G[(size_t)B_ * G4];       // per-step gates
__device__ float  g_X[(size_t)B_ * KX];       // [h | attn | 0pad]
__device__ float  g_c[(size_t)B_ * H_];       // LSTM cell state

__device__ __forceinline__ float sigf(float x) { return 1.f / (1.f + expf(-x)); }

// ---------------- tiny prep kernels ------------------------------------------
__global__ void k_prep0(const float* __restrict__ gcn_w, const float* __restrict__ gcn_wb,
                        const float* __restrict__ gcn_b, const float* __restrict__ hop_gate,
                        const float* __restrict__ attn_w) {
    int t = threadIdx.x;  // 128 threads
    if (t == 0) {
        float a = hop_gate[0], b = hop_gate[1];
        float m = fmaxf(a, b);
        float ea = expf(a - m), eb = expf(b - m);
        g_gw[0] = ea / (ea + eb);
        g_gw[1] = eb / (ea + eb);
    }
    if (t < 128) {
        g_biasvec[t] = gcn_wb[t] + gcn_b[t];
        float ur = 0.f, ue = 0.f;
        for (int d = 0; d < 128; d++) {
            float aw = attn_w[d];
            ur += gcn_w[d * 256 + t] * aw;
            ue += gcn_w[d * 256 + 128 + t] * aw;
        }
        g_u[t] = ur;
        g_u[128 + t] = ue;
    }
}

__global__ void k_tr_gcn(const float* __restrict__ gcn_w) {
    int idx = blockIdx.x * blockDim.x + threadIdx.x;  // 128*256
    if (idx >= 128 * 256) return;
    int k = idx >> 8, n = idx & 255;
    g_Wcat[idx] = (n < 128) ? gcn_w[n * 256 + k] : gcn_w[(n - 128) * 256 + 128 + k];
}

__global__ void k_tr_lstm(const float* __restrict__ w_ih, const float* __restrict__ w_hh,
                          const float* __restrict__ b_ih, const float* __restrict__ b_hh) {
    for (int idx = blockIdx.x * blockDim.x + threadIdx.x; idx < KX * G4;
         idx += gridDim.x * blockDim.x) {
        int k = idx / G4, n = idx - k * G4;
        if (k < 256) {
            g_wihT[idx]  = w_ih[n * 256 + k];
            g_Wstep[idx] = w_hh[n * 512 + k];       // Whh_h^T (h part of w_hh)
        } else {
            g_Wstep[idx] = 0.f;                      // rows 256:272 zero; sgW overwrites 256:261 later
        }
        if (idx < G4) g_bias2[idx] = b_ih[idx] + b_hh[idx];
    }
}

// ---------------- generic fp32 SGEMM: C = [Cadd +] A@B [+ bias] --------------
// A row-major [M,lda], B row-major [K,ldb], C [M,ldc]. N tiles via blockIdx.y.
// Requires: K % 16 == 0, N tile exact, lda/ldb/ldc % 4 == 0.
__global__ __launch_bounds__(256, 2) void sgemm128(
    const float* __restrict__ A, const float* __restrict__ Bm,
    float* __restrict__ C, const float* __restrict__ Cadd,
    const float* __restrict__ bias,
    int M, int K, int lda, int ldb, int ldc) {
    __shared__ float As[16][128];
    __shared__ float Bs[16][128];
    const int m0 = blockIdx.x * 128;
    const int n0 = blockIdx.y * 128;
    const int t = threadIdx.x;
    const int tr = t >> 4, tc = t & 15;

    float acc[8][8];
#pragma unroll
    for (int i = 0; i < 8; i++)
#pragma unroll
        for (int j = 0; j < 8; j++) acc[i][j] = 0.f;

    for (int k0 = 0; k0 < K; k0 += 16) {
#pragma unroll
        for (int i = 0; i < 2; i++) {
            int lin = t + i * 256;
            int row = lin >> 2, k4 = (lin & 3) * 4;
            float4 v = make_float4(0.f, 0.f, 0.f, 0.f);
            if (m0 + row < M)
                v = *(const float4*)&A[(size_t)(m0 + row) * lda + k0 + k4];
            As[k4 + 0][row] = v.x; As[k4 + 1][row] = v.y;
            As[k4 + 2][row] = v.z; As[k4 + 3][row] = v.w;
        }
#pragma unroll
        for (int i = 0; i < 2; i++) {
            int lin = t + i * 256;
            int row = lin >> 5, c4 = (lin & 31) * 4;
            *(float4*)&Bs[row][c4] =
                *(const float4*)&Bm[(size_t)(k0 + row) * ldb + n0 + c4];
        }
        __syncthreads();
#pragma unroll
        for (int kk = 0; kk < 16; kk++) {
            float a[8], b[8];
            *(float4*)&a[0] = *(const float4*)&As[kk][tr * 8];
            *(float4*)&a[4] = *(const float4*)&As[kk][tr * 8 + 4];
            *(float4*)&b[0] = *(const float4*)&Bs[kk][tc * 8];
            *(float4*)&b[4] = *(const float4*)&Bs[kk][tc * 8 + 4];
#pragma unroll
            for (int i = 0; i < 8; i++)
#pragma unroll
                for (int j = 0; j < 8; j++) acc[i][j] += a[i] * b[j];
        }
        __syncthreads();
    }

#pragma unroll
    for (int i = 0; i < 8; i++) {
        int row = m0 + tr * 8 + i;
        if (row < M) {
            int col = n0 + tc * 8;
            float o[8];
#pragma unroll
            for (int j = 0; j < 8; j++) o[j] = acc[i][j];
            if (bias) {
#pragma unroll
                for (int j = 0; j < 8; j++) o[j] += bias[col + j];
            }
            if (Cadd) {
                float4 c0 = *(const float4*)&Cadd[(size_t)row * ldc + col];
                float4 c1 = *(const float4*)&Cadd[(size_t)row * ldc + col + 4];
                o[0] += c0.x; o[1] += c0.y; o[2] += c0.z; o[3] += c0.w;
                o[4] += c1.x; o[5] += c1.y; o[6] += c1.z; o[7] += c1.w;
            }
            *(float4*)&C[(size_t)row * ldc + col]     = make_float4(o[0], o[1], o[2], o[3]);
            *(float4*)&C[(size_t)row * ldc + col + 4] = make_float4(o[4], o[5], o[6], o[7]);
        }
    }
}

// ---------------- per-symbol score scalars ------------------------------------
__global__ void k_scal(const float* __restrict__ emb) {
    __shared__ float su[256];
    int t = threadIdx.x;
    su[t] = g_u[t];
    __syncthreads();
    int warp = t >> 5, lane = t & 31;
    int s = blockIdx.x * 8 + warp;
    if (s >= NSYM) return;
    float pr = 0.f, pe = 0.f;
#pragma unroll
    for (int i = 0; i < 4; i++) {
        int k = lane + i * 32;
        float e = emb[(size_t)s * 128 + k];
        pr += e * su[k];
        pe += e * su[128 + k];
    }
#pragma unroll
    for (int o = 16; o; o >>= 1) {
        pr += __shfl_down_sync(0xffffffffu, pr, o);
        pe += __shfl_down_sync(0xffffffffu, pe, o);
    }
    if (lane == 0) g_scal[s] = make_float2(pr, pe);
}

// ---------------- neighbor encoder (4 conn tables per row) --------------------
__global__ __launch_bounds__(512) void k_neigh(
    const int* __restrict__ c0, const int* __restrict__ c1,
    const int* __restrict__ c2, const int* __restrict__ c3,
    float* __restrict__ out) {
    __shared__ int   s_idx[4][NN_][2];
    __shared__ float s_e[4][NN_];      // raw scores, then exp()
    __shared__ float s_res[4][128];
    const int n = blockIdx.x;
    const int t = threadIdx.x;
    const int g = t >> 7, r = t & 127;
    const int* cp = (g == 0) ? c0 : (g == 1) ? c1 : (g == 2) ? c2 : c3;
    {
        int j = r >> 1, w = r & 1;
        s_idx[g][j][w] = cp[((size_t)n * NN_ + j) * 2 + w];
    }
    __syncthreads();
    if (r < NN_) {
        float2 sr = g_scal[s_idx[g][r][0]];
        float2 se = g_scal[s_idx[g][r][1]];
        s_e[g][r] = sr.x + se.y;
    }
    __syncthreads();
    float mx = -1e30f;
#pragma unroll 8
    for (int j = 0; j < NN_; j++) mx = fmaxf(mx, s_e[g][j]);
    __syncthreads();
    if (r < NN_) s_e[g][r] = expf(s_e[g][r] - mx);
    __syncthreads();
    float sum = 0.f;
#pragma unroll 8
    for (int j = 0; j < NN_; j++) sum += s_e[g][j];
    float inv = 1.f / sum;

    const int d = r;
    float acc = 0.f;
#pragma unroll 4
    for (int j = 0; j < NN_; j++) {
        int rel = s_idx[g][j][0], ent = s_idx[g][j][1];
        float e = s_e[g][j];
        acc += e * (g_pe[(size_t)rel * 256 + d] + g_pe[(size_t)ent * 256 + 128 + d]);
    }
    s_res[g][d] = tanhf(acc * inv + g_biasvec[d]);
    __syncthreads();
    if (t < 256) {
        int side = t >> 7, dd = t & 127;
        int gg = side * 2;
        out[(size_t)n * 256 + t] = g_gw[0] * s_res[gg][dd] + g_gw[1] * s_res[gg + 1][dd];
    }
}

// ---------------- support encoder chain ----------------------------------------
__device__ __forceinline__ float warp_sum(float v) {
#pragma unroll
    for (int o = 16; o; o >>= 1) v += __shfl_down_sync(0xffffffffu, v, o);
    return v;
}

__global__ void k_sup1(const float* __restrict__ p1_w, const float* __restrict__ p1_b) {
    int warp = threadIdx.x >> 5, lane = threadIdx.x & 31;
    int gw = blockIdx.x * 8 + warp;   // FEW*DI warps
    if (gw >= FEW * DI) return;
    int f = gw / DI, j = gw - f * DI;
    float s = 0.f;
#pragma unroll
    for (int i = 0; i < 8; i++) {
        int k = lane + i * 32;
        s += g_sn[f * DM + k] * p1_w[j * DM + k];
    }
    s = warp_sum(s);
    if (lane == 0) g_h1[f * DI + j] = fmaxf(s + p1_b[j], 0.f);
}

__global__ void k_sup2(const float* __restrict__ p2_w, const float* __restrict__ p2_b) {
    int warp = threadIdx.x >> 5, lane = threadIdx.x & 31;
    int gw = blockIdx.x * 8 + warp;   // FEW*DM warps
    if (gw >= FEW * DM) return;
    int f = gw / DM, d = gw - f * DM;
    float s = 0.f;
#pragma unroll
    for (int i = 0; i < 16; i++) {
        int k = lane + i * 32;
        s += g_h1[f * DI + k] * p2_w[d * DI + k];
    }
    s = warp_sum(s);
    if (lane == 0) g_z[f * DM + d] = s + p2_b[d] + g_sn[f * DM + d];
}

__global__ void k_ln(const float* __restrict__ ln_g, const float* __restrict__ ln_b) {
    __shared__ float sred[8];
    int f = blockIdx.x, t = threadIdx.x;  // 256 threads
    float z = g_z[f * DM + t];
    int lane = t & 31, warp = t >> 5;

    float v = warp_sum(z);
    if (lane == 0) sred[warp] = v;
    __syncthreads();
    if (t == 0) {
        float s = 0.f;
        for (int w = 0; w < 8; w++) s += sred[w];
        sred[0] = s * (1.f / 256.f);
    }
    __syncthreads();
    float mu = sred[0];
    __syncthreads();
    float dv = z - mu;
    float v2 = warp_sum(dv * dv);
    if (lane == 0) sred[warp] = v2;
    __syncthreads();
    if (t == 0) {
        float s = 0.f;
        for (int w = 0; w < 8; w++) s += sred[w];
        sred[0] = s * (1.f / 256.f);
    }
    __syncthreads();
    float var = sred[0];
    g_sg[f * DM + t] = dv * rsqrtf(var + 1e-6f) * ln_g[t] + ln_b[t];
}

__global__ void k_sm_mean() {
    int t = threadIdx.x;  // 256
    float s = 0.f;
#pragma unroll
    for (int f = 0; f < FEW; f++) s += g_sg[f * DM + t];
    g_sm[t] = s * (1.f / (float)FEW);
}

__global__ void k_sgw(const float* __restrict__ w_hh) {
    int warp = threadIdx.x >> 5, lane = threadIdx.x & 31;
    int gw = blockIdx.x * 8 + warp;   // FEW*G4 warps
    if (gw >= FEW * G4) return;
    int f = gw / G4, n = gw - f * G4;
    float s = 0.f;
#pragma unroll
    for (int i = 0; i < 8; i++) {
        int k = lane + i * 32;
        s += g_sg[f * DM + k] * w_hh[n * 512 + 256 + k];
    }
    s = warp_sum(s);
    if (lane == 0) g_Wstep[(256 + f) * G4 + n] = s;
}

// ---------------- fused LSTM cell + h update + attn softmax -------------------
__global__ __launch_bounds__(256) void k_lstm(const float* __restrict__ gates,
                                              int first, int last,
                                              float* __restrict__ out) {
    __shared__ float red[8][5];
    const int b = blockIdx.x, t = threadIdx.x;
    const float* gr = gates + (size_t)b * G4;
    float hv = 0.f;
#pragma unroll
    for (int jj = 0; jj < 2; jj++) {
        int j = t + jj * 256;
        float gi = gr[j], gf = gr[512 + j], gg = gr[1024 + j], go = gr[1536 + j];
        float cold = first ? 0.f : g_c[(size_t)b * 512 + j];
        float cn = sigf(gf) * cold + sigf(gi) * tanhf(gg);
        float hc = sigf(go) * tanhf(cn);
        g_c[(size_t)b * 512 + j] = cn;
        if (jj == 0) {
            hv = g_qn[(size_t)b * 256 + t] + hc;
            g_X[(size_t)b * KX + t] = hv;
        }
    }
    if (first && t < (KX - 261)) g_X[(size_t)b * KX + 261 + t] = 0.f;  // zero pad cols once

    int lane = t & 31, warp = t >> 5;
    if (last) {
        float p = hv * g_sm[t];
        p = warp_sum(p);
        if (lane == 0) red[warp][0] = p;
        __syncthreads();
        if (t == 0) {
            float s = 0.f;
            for (int w = 0; w < 8; w++) s += red[w][0];
            out[b] = s;
        }
    } else {
        float p[FEW];
#pragma unroll
        for (int f = 0; f < FEW; f++) p[f] = hv * g_sg[f * DM + t];
#pragma unroll
        for (int f = 0; f < FEW; f++) p[f] = warp_sum(p[f]);
        if (lane == 0)
#pragma unroll
            for (int f = 0; f < FEW; f++) red[warp][f] = p[f];
        __syncthreads();
        if (t == 0) {
            float s[FEW];
#pragma unroll
            for (int f = 0; f < FEW; f++) {
                float acc = 0.f;
                for (int w = 0; w < 8; w++) acc += red[w][f];
                s[f] = acc;
            }
            float m = s[0];
#pragma unroll
            for (int f = 1; f < FEW; f++) m = fmaxf(m, s[f]);
            float e[FEW], se = 0.f;
#pragma unroll
            for (int f = 0; f < FEW; f++) { e[f] = expf(s[f] - m); se += e[f]; }
            float inv = 1.f / se;
#pragma unroll
            for (int f = 0; f < FEW; f++) g_X[(size_t)b * KX + 256 + f] = e[f] * inv;
        }
    }
}

// ---------------- host launcher ------------------------------------------------
template <typename T>
static float* symaddr(T& sym) {
    void* p = nullptr;
    cudaGetSymbolAddress(&p, sym);
    return (float*)p;
}

extern "C" void kernel_launch(void* const* d_in, const int* in_sizes, int n_in,
                              void* d_out, int out_size) {
    const int* q_l1 = (const int*)d_in[0];
    const int* q_l2 = (const int*)d_in[1];
    const int* q_r1 = (const int*)d_in[2];
    const int* q_r2 = (const int*)d_in[3];
    const int* s_l1 = (const int*)d_in[4];
    const int* s_l2 = (const int*)d_in[5];
    const int* s_r1 = (const int*)d_in[6];
    const int* s_r2 = (const int*)d_in[7];
    // d_in[8..11] = degrees (unused by the reference math)
    const float* emb      = (const float*)d_in[12];
    const float* gcn_w    = (const float*)d_in[13];
    const float* gcn_wb   = (const float*)d_in[14];
    const float* gcn_b    = (const float*)d_in[15];
    const float* hop_gate = (const float*)d_in[16];
    const float* attn_w   = (const float*)d_in[17];
    // d_in[18] attn_b: constant shift, cancels in softmax
    const float* p1_w = (const float*)d_in[19];
    const float* p1_b = (const float*)d_in[20];
    const float* p2_w = (const float*)d_in[21];
    const float* p2_b = (const float*)d_in[22];
    const float* ln_g = (const float*)d_in[23];
    const float* ln_b = (const float*)d_in[24];
    const float* w_ih = (const float*)d_in[25];
    const float* w_hh = (const float*)d_in[26];
    const float* b_ih = (const float*)d_in[27];
    const float* b_hh = (const float*)d_in[28];
    float* out = (float*)d_out;

    float* pPe    = symaddr(g_pe);
    float* pWcat  = symaddr(g_Wcat);
    float* pQn    = symaddr(g_qn);
    float* pSn    = symaddr(g_sn);
    float* pWihT  = symaddr(g_wihT);
    float* pWstep = symaddr(g_Wstep);
    float* pBias2 = symaddr(g_bias2);
    float* pA     = symaddr(g_A);
    float* pG     = symaddr(g_G);
    float* pX     = symaddr(g_X);

    // prep
    k_prep0<<<1, 128>>>(gcn_w, gcn_wb, gcn_b, hop_gate, attn_w);
    k_tr_gcn<<<(128 * 256 + 255) / 256, 256>>>(gcn_w);
    k_tr_lstm<<<2176, 256>>>(w_ih, w_hh, b_ih, b_hh);

    // pe = emb @ Wcat   [100000,128]@[128,256]
    sgemm128<<<dim3((NSYM + 127) / 128, 256 / 128), 256>>>(
        emb, pWcat, pPe, nullptr, nullptr, NSYM, 128, 128, 256, 256);
    k_scal<<<NSYM / 8, 256>>>(emb);

    // neighbor encoders
    k_neigh<<<B_, 512>>>(q_l1, q_l2, q_r1, q_r2, pQn);
    k_neigh<<<FEW, 512>>>(s_l1, s_l2, s_r1, s_r2, pSn);

    // support encoder
    k_sup1<<<(FEW * DI) / 8, 256>>>(p1_w, p1_b);
    k_sup2<<<(FEW * DM) / 8, 256>>>(p2_w, p2_b);
    k_ln<<<FEW, 256>>>(ln_g, ln_b);
    k_sm_mean<<<1, 256>>>();
    k_sgw<<<(FEW * G4) / 8, 256>>>(w_hh);

    // A = qn @ w_ih.T + (b_ih + b_hh)   [4096,256]@[256,2048]
    sgemm128<<<dim3(B_ / 128, G4 / 128), 256>>>(
        pQn, pWihT, pA, nullptr, pBias2, B_, 256, 256, G4, G4);

    // step 1: gates = A (h_r = 0)
    k_lstm<<<B_, 256>>>(pA, 1, 0, out);

    // steps 2..4: G = A + [h|attn|0] @ Wstep   [4096,272]@[272,2048]
    for (int s = 2; s <= 4; s++) {
        sgemm128<<<dim3(B_ / 128, G4 / 128), 256>>>(
            pX, pWstep, pG, pA, nullptr, B_, KX, KX, G4, G4);
        k_lstm<<<B_, 256>>>(pG, 0, (s == 4) ? 1 : 0, out);
    }
}

// round 3
// speedup vs baseline: 1.7993x; 1.7993x over previous
#include <cuda_runtime.h>
#include <math.h>

#define B_    4096
#define FEW   5
#define NN_   64
#define NSYM  100000
#define DM    256
#define DI    512
#define G1K   1024   // reduced gate width (only first 256 of each of i,f,g,o matter)
#define KX    272    // padded K for step GEMM: 256 (h) + 5 (attn) + 11 pad
#define YROWS (B_ * 4 + FEW * 4)   // 16404

typedef unsigned long long u64;

// ---------------- scratch (static device globals; no allocation) -------------
__device__ float2 g_scal[NSYM];                // per-symbol score scalars (rel, ent)
__device__ float  g_Wg[256 * 128];             // k-major gcn weight  [k][d]
__device__ float  g_u[2 * 128];                // folded attn vectors (rel, ent)
__device__ float  g_gw[2];                     // softmax(hop_gate)
__device__ float  g_biasvec[128];              // gcn_wb + gcn_b
__device__ float  g_Y[(size_t)(YROWS + 12) * 256];  // weighted concat-embedding sums
__device__ float  g_P[(size_t)(YROWS + 12) * 128];  // Y @ Wg + bias
__device__ float  g_qn[(size_t)B_ * DM];       // query_neighbor
__device__ float  g_sn[FEW * DM];              // support_neighbor
__device__ float  g_h1[FEW * DI];
__device__ float  g_z[FEW * DM];
__device__ float  g_sg[FEW * DM];              // support_g
__device__ float  g_sm[DM];                    // support mean
__device__ float  g_wihT[DM * G1K];            // reduced w_ih^T  [256,1024]
__device__ float  g_Wstep[KX * G1K];           // rows 0:256 = Whh_h^T, 256:261 = sgW, rest 0
__device__ float  g_bias2[G1K];                // b_ih + b_hh (reduced cols)
__device__ float  g_A[(size_t)B_ * G1K];       // q @ w_ih.T + bias
__device__ float  g_G[(size_t)B_ * G1K];       // per-step gates
__device__ float  g_X[(size_t)B_ * KX];        // [h | attn | 0pad]
__device__ float  g_c[(size_t)B_ * 256];       // LSTM cell state (live part only)

__device__ __forceinline__ float sigf(float x) { return 1.f / (1.f + expf(-x)); }

__device__ __forceinline__ u64 pack2(float x, float y) {
    u64 r;
    asm("mov.b64 %0, {%1,%2};" : "=l"(r) : "f"(x), "f"(y));
    return r;
}
__device__ __forceinline__ void unpack2(u64 v, float& x, float& y) {
    asm("mov.b64 {%0,%1}, %2;" : "=f"(x), "=f"(y) : "l"(v));
}
__device__ __forceinline__ void ffma2(u64& acc, u64 a, u64 b) {
    asm("fma.rn.f32x2 %0, %1, %2, %0;" : "+l"(acc) : "l"(a), "l"(b));
}

// ---------------- tiny prep kernels ------------------------------------------
__global__ void k_prep0(const float* __restrict__ gcn_w, const float* __restrict__ gcn_wb,
                        const float* __restrict__ gcn_b, const float* __restrict__ hop_gate,
                        const float* __restrict__ attn_w) {
    int t = threadIdx.x;  // 128
    if (t == 0) {
        float a = hop_gate[0], b = hop_gate[1];
        float m = fmaxf(a, b);
        float ea = expf(a - m), eb = expf(b - m);
        g_gw[0] = ea / (ea + eb);
        g_gw[1] = eb / (ea + eb);
    }
    if (t < 128) {
        g_biasvec[t] = gcn_wb[t] + gcn_b[t];
        float ur = 0.f, ue = 0.f;
        for (int d = 0; d < 128; d++) {
            float aw = attn_w[d];
            ur += gcn_w[d * 256 + t] * aw;
            ue += gcn_w[d * 256 + 128 + t] * aw;
        }
        g_u[t] = ur;
        g_u[128 + t] = ue;
    }
}

__global__ void k_tr_gcn(const float* __restrict__ gcn_w) {
    int idx = blockIdx.x * blockDim.x + threadIdx.x;  // 256*128
    if (idx >= 256 * 128) return;
    int k = idx >> 7, d = idx & 127;
    g_Wg[idx] = gcn_w[d * 256 + k];
}

__global__ void k_tr_lstm(const float* __restrict__ w_ih, const float* __restrict__ w_hh,
                          const float* __restrict__ b_ih, const float* __restrict__ b_hh) {
    for (int idx = blockIdx.x * blockDim.x + threadIdx.x; idx < KX * G1K;
         idx += gridDim.x * blockDim.x) {
        int k = idx / G1K, n = idx - k * G1K;
        int src = ((n >> 8) << 9) + (n & 255);  // gate-block g -> row g*512 + (n%256)
        if (k < 256) {
            g_wihT[idx]  = w_ih[src * 256 + k];
            g_Wstep[idx] = w_hh[src * 512 + k];
        } else {
            g_Wstep[idx] = 0.f;
        }
        if (idx < G1K) g_bias2[idx] = b_ih[src] + b_hh[src];
    }
}

// ---------------- fp32 SGEMM with FFMA2 inner loop ----------------------------
// C[M,ldc] = [Cadd +] A[M,lda] @ B[K,ldb] [+ bias]; K%16==0, N tile exact.
__global__ __launch_bounds__(256, 2) void sgemm128(
    const float* __restrict__ A, const float* __restrict__ Bm,
    float* __restrict__ C, const float* __restrict__ Cadd,
    const float* __restrict__ bias,
    int M, int K, int lda, int ldb, int ldc) {
    __shared__ float As[16][128];
    __shared__ float Bs[16][128];
    const int m0 = blockIdx.x * 128;
    const int n0 = blockIdx.y * 128;
    const int t = threadIdx.x;
    const int tr = t >> 4, tc = t & 15;

    u64 acc[4][8];  // row-pairs (2 consecutive m) x 8 n
#pragma unroll
    for (int i = 0; i < 4; i++)
#pragma unroll
        for (int j = 0; j < 8; j++) acc[i][j] = 0ull;

    for (int k0 = 0; k0 < K; k0 += 16) {
#pragma unroll
        for (int i = 0; i < 2; i++) {
            int lin = t + i * 256;
            int row = lin >> 2, k4 = (lin & 3) * 4;
            float4 v = make_float4(0.f, 0.f, 0.f, 0.f);
            if (m0 + row < M)
                v = *(const float4*)&A[(size_t)(m0 + row) * lda + k0 + k4];
            As[k4 + 0][row] = v.x; As[k4 + 1][row] = v.y;
            As[k4 + 2][row] = v.z; As[k4 + 3][row] = v.w;
        }
#pragma unroll
        for (int i = 0; i < 2; i++) {
            int lin = t + i * 256;
            int row = lin >> 5, c4 = (lin & 31) * 4;
            *(float4*)&Bs[row][c4] =
                *(const float4*)&Bm[(size_t)(k0 + row) * ldb + n0 + c4];
        }
        __syncthreads();
#pragma unroll
        for (int kk = 0; kk < 16; kk++) {
            float4 a0 = *(const float4*)&As[kk][tr * 8];
            float4 a1 = *(const float4*)&As[kk][tr * 8 + 4];
            float4 b0 = *(const float4*)&Bs[kk][tc * 8];
            float4 b1 = *(const float4*)&Bs[kk][tc * 8 + 4];
            u64 ap0 = pack2(a0.x, a0.y), ap1 = pack2(a0.z, a0.w);
            u64 ap2 = pack2(a1.x, a1.y), ap3 = pack2(a1.z, a1.w);
            float bs[8] = {b0.x, b0.y, b0.z, b0.w, b1.x, b1.y, b1.z, b1.w};
#pragma unroll
            for (int j = 0; j < 8; j++) {
                u64 bd = pack2(bs[j], bs[j]);
                ffma2(acc[0][j], ap0, bd);
                ffma2(acc[1][j], ap1, bd);
                ffma2(acc[2][j], ap2, bd);
                ffma2(acc[3][j], ap3, bd);
            }
        }
        __syncthreads();
    }

#pragma unroll
    for (int ip = 0; ip < 4; ip++) {
#pragma unroll
        for (int half = 0; half < 2; half++) {
            int row = m0 + tr * 8 + 2 * ip + half;
            if (row < M) {
                int col = n0 + tc * 8;
                float o[8];
#pragma unroll
                for (int j = 0; j < 8; j++) {
                    float lo, hi;
                    unpack2(acc[ip][j], lo, hi);
                    o[j] = half ? hi : lo;
                }
                if (bias) {
#pragma unroll
                    for (int j = 0; j < 8; j++) o[j] += bias[col + j];
                }
                if (Cadd) {
                    float4 c0 = *(const float4*)&Cadd[(size_t)row * ldc + col];
                    float4 c1 = *(const float4*)&Cadd[(size_t)row * ldc + col + 4];
                    o[0] += c0.x; o[1] += c0.y; o[2] += c0.z; o[3] += c0.w;
                    o[4] += c1.x; o[5] += c1.y; o[6] += c1.z; o[7] += c1.w;
                }
                *(float4*)&C[(size_t)row * ldc + col]     = make_float4(o[0], o[1], o[2], o[3]);
                *(float4*)&C[(size_t)row * ldc + col + 4] = make_float4(o[4], o[5], o[6], o[7]);
            }
        }
    }
}

// ---------------- per-symbol score scalars ------------------------------------
__global__ void k_scal(const float* __restrict__ emb) {
    __shared__ float su[256];
    int t = threadIdx.x;
    su[t] = g_u[t];
    __syncthreads();
    int warp = t >> 5, lane = t & 31;
    int s = blockIdx.x * 8 + warp;
    if (s >= NSYM) return;
    float pr = 0.f, pe = 0.f;
#pragma unroll
    for (int i = 0; i < 4; i++) {
        int k = lane + i * 32;
        float e = emb[(size_t)s * 128 + k];
        pr += e * su[k];
        pe += e * su[128 + k];
    }
#pragma unroll
    for (int o = 16; o; o >>= 1) {
        pr += __shfl_down_sync(0xffffffffu, pr, o);
        pe += __shfl_down_sync(0xffffffffu, pe, o);
    }
    if (lane == 0) g_scal[s] = make_float2(pr, pe);
}

// ---------------- neighbor encoder: softmax + weighted embedding sums ----------
__global__ __launch_bounds__(512) void k_neigh(
    const int* __restrict__ c0, const int* __restrict__ c1,
    const int* __restrict__ c2, const int* __restrict__ c3,
    const float* __restrict__ emb, int rowbase) {
    __shared__ int   s_idx[4][NN_][2];
    __shared__ float s_e[4][NN_];
    const int n = blockIdx.x;
    const int t = threadIdx.x;
    const int g = t >> 7, r = t & 127;
    const int* cp = (g == 0) ? c0 : (g == 1) ? c1 : (g == 2) ? c2 : c3;
    {
        int j = r >> 1, w = r & 1;
        s_idx[g][j][w] = cp[((size_t)n * NN_ + j) * 2 + w];
    }
    __syncthreads();
    if (r < NN_) {
        float2 sr = g_scal[s_idx[g][r][0]];
        float2 se = g_scal[s_idx[g][r][1]];
        s_e[g][r] = sr.x + se.y;
    }
    __syncthreads();
    float mx = -1e30f;
#pragma unroll 8
    for (int j = 0; j < NN_; j++) mx = fmaxf(mx, s_e[g][j]);
    __syncthreads();
    if (r < NN_) s_e[g][r] = expf(s_e[g][r] - mx);
    __syncthreads();
    float sum = 0.f;
#pragma unroll 8
    for (int j = 0; j < NN_; j++) sum += s_e[g][j];
    float inv = 1.f / sum;

    float accR = 0.f, accE = 0.f;
#pragma unroll 4
    for (int j = 0; j < NN_; j++) {
        float w = s_e[g][j] * inv;
        accR += w * __ldg(&emb[(size_t)s_idx[g][j][0] * 128 + r]);
        accE += w * __ldg(&emb[(size_t)s_idx[g][j][1] * 128 + r]);
    }
    size_t yrow = (size_t)(rowbase + n * 4 + g) * 256;
    g_Y[yrow + r]       = accR;
    g_Y[yrow + 128 + r] = accE;
}

// ---------------- combine: tanh + hop-gate mix ---------------------------------
__global__ void k_mix(float* __restrict__ out, int rowbase) {
    int n = blockIdx.x, t = threadIdx.x;  // 256
    int side = t >> 7, d = t & 127;
    size_t r0 = (size_t)(rowbase + n * 4 + side * 2) * 128;
    float v = g_gw[0] * tanhf(g_P[r0 + d]) + g_gw[1] * tanhf(g_P[r0 + 128 + d]);
    out[(size_t)n * 256 + t] = v;
}

// ---------------- support encoder chain ----------------------------------------
__device__ __forceinline__ float warp_sum(float v) {
#pragma unroll
    for (int o = 16; o; o >>= 1) v += __shfl_down_sync(0xffffffffu, v, o);
    return v;
}

__global__ void k_sup1(const float* __restrict__ p1_w, const float* __restrict__ p1_b) {
    int warp = threadIdx.x >> 5, lane = threadIdx.x & 31;
    int gw = blockIdx.x * 8 + warp;
    if (gw >= FEW * DI) return;
    int f = gw / DI, j = gw - f * DI;
    float s = 0.f;
#pragma unroll
    for (int i = 0; i < 8; i++) {
        int k = lane + i * 32;
        s += g_sn[f * DM + k] * p1_w[j * DM + k];
    }
    s = warp_sum(s);
    if (lane == 0) g_h1[f * DI + j] = fmaxf(s + p1_b[j], 0.f);
}

__global__ void k_sup2(const float* __restrict__ p2_w, const float* __restrict__ p2_b) {
    int warp = threadIdx.x >> 5, lane = threadIdx.x & 31;
    int gw = blockIdx.x * 8 + warp;
    if (gw >= FEW * DM) return;
    int f = gw / DM, d = gw - f * DM;
    float s = 0.f;
#pragma unroll
    for (int i = 0; i < 16; i++) {
        int k = lane + i * 32;
        s += g_h1[f * DI + k] * p2_w[d * DI + k];
    }
    s = warp_sum(s);
    if (lane == 0) g_z[f * DM + d] = s + p2_b[d] + g_sn[f * DM + d];
}

__global__ void k_ln(const float* __restrict__ ln_g, const float* __restrict__ ln_b) {
    __shared__ float sred[8];
    int f = blockIdx.x, t = threadIdx.x;  // 256
    float z = g_z[f * DM + t];
    int lane = t & 31, warp = t >> 5;

    float v = warp_sum(z);
    if (lane == 0) sred[warp] = v;
    __syncthreads();
    if (t == 0) {
        float s = 0.f;
        for (int w = 0; w < 8; w++) s += sred[w];
        sred[0] = s * (1.f / 256.f);
    }
    __syncthreads();
    float mu = sred[0];
    __syncthreads();
    float dv = z - mu;
    float v2 = warp_sum(dv * dv);
    if (lane == 0) sred[warp] = v2;
    __syncthreads();
    if (t == 0) {
        float s = 0.f;
        for (int w = 0; w < 8; w++) s += sred[w];
        sred[0] = s * (1.f / 256.f);
    }
    __syncthreads();
    float var = sred[0];
    g_sg[f * DM + t] = dv * rsqrtf(var + 1e-6f) * ln_g[t] + ln_b[t];
}

__global__ void k_sm_mean() {
    int t = threadIdx.x;  // 256
    float s = 0.f;
#pragma unroll
    for (int f = 0; f < FEW; f++) s += g_sg[f * DM + t];
    g_sm[t] = s * (1.f / (float)FEW);
}

__global__ void k_sgw(const float* __restrict__ w_hh) {
    int warp = threadIdx.x >> 5, lane = threadIdx.x & 31;
    int gw = blockIdx.x * 8 + warp;
    if (gw >= FEW * G1K) return;
    int f = gw / G1K, n = gw - f * G1K;
    int src = ((n >> 8) << 9) + (n & 255);
    float s = 0.f;
#pragma unroll
    for (int i = 0; i < 8; i++) {
        int k = lane + i * 32;
        s += g_sg[f * DM + k] * w_hh[src * 512 + 256 + k];
    }
    s = warp_sum(s);
    if (lane == 0) g_Wstep[(256 + f) * G1K + n] = s;
}

// ---------------- fused LSTM cell + h update + attn softmax -------------------
__global__ __launch_bounds__(256) void k_lstm(const float* __restrict__ gates,
                                              int first, int last,
                                              float* __restrict__ out) {
    __shared__ float red[8][5];
    const int b = blockIdx.x, t = threadIdx.x;
    const float* gr = gates + (size_t)b * G1K;
    float gi = gr[t], gf = gr[256 + t], gg = gr[512 + t], go = gr[768 + t];
    float cold = first ? 0.f : g_c[(size_t)b * 256 + t];
    float cn = sigf(gf) * cold + sigf(gi) * tanhf(gg);
    float hc = sigf(go) * tanhf(cn);
    g_c[(size_t)b * 256 + t] = cn;
    float hv = g_qn[(size_t)b * 256 + t] + hc;
    g_X[(size_t)b * KX + t] = hv;
    if (first && t < (KX - 261)) g_X[(size_t)b * KX + 261 + t] = 0.f;

    int lane = t & 31, warp = t >> 5;
    if (last) {
        float p = warp_sum(hv * g_sm[t]);
        if (lane == 0) red[warp][0] = p;
        __syncthreads();
        if (t == 0) {
            float s = 0.f;
            for (int w = 0; w < 8; w++) s += red[w][0];
            out[b] = s;
        }
    } else {
        float p[FEW];
#pragma unroll
        for (int f = 0; f < FEW; f++) p[f] = warp_sum(hv * g_sg[f * DM + t]);
        if (lane == 0)
#pragma unroll
            for (int f = 0; f < FEW; f++) red[warp][f] = p[f];
        __syncthreads();
        if (t == 0) {
            float s[FEW];
#pragma unroll
            for (int f = 0; f < FEW; f++) {
                float acc = 0.f;
                for (int w = 0; w < 8; w++) acc += red[w][f];
                s[f] = acc;
            }
            float m = s[0];
#pragma unroll
            for (int f = 1; f < FEW; f++) m = fmaxf(m, s[f]);
            float e[FEW], se = 0.f;
#pragma unroll
            for (int f = 0; f < FEW; f++) { e[f] = expf(s[f] - m); se += e[f]; }
            float inv = 1.f / se;
#pragma unroll
            for (int f = 0; f < FEW; f++) g_X[(size_t)b * KX + 256 + f] = e[f] * inv;
        }
    }
}

// ---------------- host launcher ------------------------------------------------
template <typename T>
static float* symaddr(T& sym) {
    void* p = nullptr;
    cudaGetSymbolAddress(&p, sym);
    return (float*)p;
}

extern "C" void kernel_launch(void* const* d_in, const int* in_sizes, int n_in,
                              void* d_out, int out_size) {
    const int* q_l1 = (const int*)d_in[0];
    const int* q_l2 = (const int*)d_in[1];
    const int* q_r1 = (const int*)d_in[2];
    const int* q_r2 = (const int*)d_in[3];
    const int* s_l1 = (const int*)d_in[4];
    const int* s_l2 = (const int*)d_in[5];
    const int* s_r1 = (const int*)d_in[6];
    const int* s_r2 = (const int*)d_in[7];
    const float* emb      = (const float*)d_in[12];
    const float* gcn_w    = (const float*)d_in[13];
    const float* gcn_wb   = (const float*)d_in[14];
    const float* gcn_b    = (const float*)d_in[15];
    const float* hop_gate = (const float*)d_in[16];
    const float* attn_w   = (const float*)d_in[17];
    const float* p1_w = (const float*)d_in[19];
    const float* p1_b = (const float*)d_in[20];
    const float* p2_w = (const float*)d_in[21];
    const float* p2_b = (const float*)d_in[22];
    const float* ln_g = (const float*)d_in[23];
    const float* ln_b = (const float*)d_in[24];
    const float* w_ih = (const float*)d_in[25];
    const float* w_hh = (const float*)d_in[26];
    const float* b_ih = (const float*)d_in[27];
    const float* b_hh = (const float*)d_in[28];
    float* out = (float*)d_out;

    float* pWg    = symaddr(g_Wg);
    float* pY     = symaddr(g_Y);
    float* pP     = symaddr(g_P);
    float* pQn    = symaddr(g_qn);
    float* pSn    = symaddr(g_sn);
    float* pWihT  = symaddr(g_wihT);
    float* pWstep = symaddr(g_Wstep);
    float* pBias2 = symaddr(g_bias2);
    float* pBiasV = symaddr(g_biasvec);
    float* pA     = symaddr(g_A);
    float* pG     = symaddr(g_G);
    float* pX     = symaddr(g_X);

    // prep
    k_prep0<<<1, 128>>>(gcn_w, gcn_wb, gcn_b, hop_gate, attn_w);
    k_tr_gcn<<<(256 * 128 + 255) / 256, 256>>>(gcn_w);
    k_tr_lstm<<<1088, 256>>>(w_ih, w_hh, b_ih, b_hh);
    k_scal<<<NSYM / 8, 256>>>(emb);

    // neighbor encoders: weighted embedding sums into Y
    k_neigh<<<B_, 512>>>(q_l1, q_l2, q_r1, q_r2, emb, 0);
    k_neigh<<<FEW, 512>>>(s_l1, s_l2, s_r1, s_r2, emb, B_ * 4);

    // P = Y @ Wg + biasvec   [16404,256]@[256,128]
    sgemm128<<<dim3((YROWS + 127) / 128, 1), 256>>>(
        pY, pWg, pP, nullptr, pBiasV, YROWS, 256, 256, 128, 128);

    // tanh + hop-gate mix
    k_mix<<<B_, 256>>>(pQn, 0);
    k_mix<<<FEW, 256>>>(pSn, B_ * 4);

    // support encoder
    k_sup1<<<(FEW * DI) / 8, 256>>>(p1_w, p1_b);
    k_sup2<<<(FEW * DM) / 8, 256>>>(p2_w, p2_b);
    k_ln<<<FEW, 256>>>(ln_g, ln_b);
    k_sm_mean<<<1, 256>>>();
    k_sgw<<<(FEW * G1K + 7) / 8, 256>>>(w_hh);

    // A = qn @ w_ih.T + (b_ih + b_hh)   [4096,256]@[256,1024]
    sgemm128<<<dim3(B_ / 128, G1K / 128), 256>>>(
        pQn, pWihT, pA, nullptr, pBias2, B_, 256, 256, G1K, G1K);

    // step 1: gates = A (h_r = 0)
    k_lstm<<<B_, 256>>>(pA, 1, 0, out);

    // steps 2..4: G = A + [h|attn|0] @ Wstep   [4096,272]@[272,1024]
    for (int s = 2; s <= 4; s++) {
        sgemm128<<<dim3(B_ / 128, G1K / 128), 256>>>(
            pX, pWstep, pG, pA, nullptr, B_, KX, KX, G1K, G1K);
        k_lstm<<<B_, 256>>>(pG, 0, (s == 4) ? 1 : 0, out);
    }
}

// round 5
// speedup vs baseline: 2.2761x; 1.2650x over previous
#include <cuda_runtime.h>
#include <cuda_bf16.h>
#include <math.h>
#include <stdint.h>

#define B_    4096
#define FEW   5
#define NN_   64
#define NSYM  100000
#define DM    256
#define DI    512
#define G1K   1024
#define KX    272
#define YROWS (B_ * 4 + FEW * 4)   // 16404

// ---------------- scratch (static device globals; no allocation) -------------
__device__ float2 g_scal[NSYM];
__device__ float  g_u[2 * 128];
__device__ float  g_gw[2];
__device__ float  g_biasvec[128];
__device__ float  g_Y[(size_t)(YROWS + 12) * 256];
__device__ float  g_P[(size_t)(YROWS + 12) * 128];
__device__ float  g_qn[(size_t)B_ * DM];
__device__ float  g_sn[FEW * DM];
__device__ float  g_h1[FEW * DI];
__device__ float  g_z[FEW * DM];
__device__ float  g_sg[FEW * DM];
__device__ float  g_sm[DM];
__device__ float  g_WihN[1024 * 256];    // [N=1024][K=256] row-gathered w_ih
__device__ float  g_WstepN[1024 * 272];  // [N=1024][K=272]: w_hh-h | sgW | zeros
__device__ float  g_bias2[G1K];
__device__ float  g_A[(size_t)B_ * G1K];
__device__ float  g_G[(size_t)B_ * G1K];
__device__ float  g_X[(size_t)B_ * KX];
__device__ float  g_c[(size_t)B_ * 256];

__device__ __forceinline__ float sigf(float x) { return 1.f / (1.f + expf(-x)); }

// ---------------- mma.sync bf16x3 GEMM: C = [Cadd +] A@B^T [+ bias] ----------
// A [M,lda] fp32 row-major; B [Ntot,ldb] fp32 row-major. Tile 128x128.
// K in chunks of 32 (zero-padded past Kact; Kact % 16 == 0 required).
#define KC 32
#define SMS 40   // smem row stride in bf16 (32 data + 8 pad) -> conflict-free

__device__ __forceinline__ uint32_t pack_bf16_hi(float x, float y,
                                                 uint32_t& lo_out) {
    __nv_bfloat16 hx = __float2bfloat16(x);
    __nv_bfloat16 hy = __float2bfloat16(y);
    float rx = x - __bfloat162float(hx);
    float ry = y - __bfloat162float(hy);
    __nv_bfloat16 lx = __float2bfloat16(rx);
    __nv_bfloat16 ly = __float2bfloat16(ry);
    uint32_t hi = (uint32_t)*(uint16_t*)&hx | ((uint32_t)*(uint16_t*)&hy << 16);
    lo_out = (uint32_t)*(uint16_t*)&lx | ((uint32_t)*(uint16_t*)&ly << 16);
    return hi;
}

__device__ __forceinline__ void mma16816(float* d, const uint32_t* a,
                                         const uint32_t* b) {
    asm volatile(
        "mma.sync.aligned.m16n8k16.row.col.f32.bf16.bf16.f32 "
        "{%0,%1,%2,%3}, {%4,%5,%6,%7}, {%8,%9}, {%0,%1,%2,%3};"
        : "+f"(d[0]), "+f"(d[1]), "+f"(d[2]), "+f"(d[3])
        : "r"(a[0]), "r"(a[1]), "r"(a[2]), "r"(a[3]), "r"(b[0]), "r"(b[1]));
}

__global__ __launch_bounds__(256, 2) void gemm_tc(
    const float* __restrict__ A, int lda, int M,
    const float* __restrict__ B, int ldb,
    float* __restrict__ C, int ldc,
    const float* __restrict__ Cadd, const float* __restrict__ bias,
    int Kact, int NC) {
    __shared__ uint16_t sAh[128 * SMS];
    __shared__ uint16_t sAl[128 * SMS];
    __shared__ uint16_t sBh[128 * SMS];
    __shared__ uint16_t sBl[128 * SMS];

    const int t = threadIdx.x;
    const int w = t >> 5, lane = t & 31;
    const int g = lane >> 2, tig = lane & 3;
    const int m0 = blockIdx.x * 128, n0 = blockIdx.y * 128;
    const int mw = (w & 3) * 32;   // warp m offset
    const int nw = (w >> 2) * 64;  // warp n offset

    float acc[2][8][4];
#pragma unroll
    for (int mt = 0; mt < 2; mt++)
#pragma unroll
        for (int nt = 0; nt < 8; nt++)
#pragma unroll
            for (int e = 0; e < 4; e++) acc[mt][nt][e] = 0.f;

    const int lrow = t >> 1;          // 0..127
    const int lhalf = (t & 1) * 16;   // k offset within chunk
    const bool mok = (m0 + lrow) < M;
    const size_t arow = (size_t)(m0 + lrow) * lda;
    const size_t brow = (size_t)(n0 + lrow) * ldb;
    const int sbase = lrow * SMS + lhalf;

    for (int c = 0; c < NC; c++) {
        const int kk0 = c * KC + lhalf;
        __syncthreads();
        {
            float fa[16];
            if (mok && kk0 < Kact) {
#pragma unroll
                for (int q = 0; q < 4; q++) {
                    float4 v = *(const float4*)&A[arow + kk0 + q * 4];
                    fa[q * 4] = v.x; fa[q * 4 + 1] = v.y;
                    fa[q * 4 + 2] = v.z; fa[q * 4 + 3] = v.w;
                }
            } else {
#pragma unroll
                for (int e = 0; e < 16; e++) fa[e] = 0.f;
            }
#pragma unroll
            for (int p = 0; p < 8; p++) {
                uint32_t lo;
                uint32_t hi = pack_bf16_hi(fa[2 * p], fa[2 * p + 1], lo);
                *(uint32_t*)&sAh[sbase + 2 * p] = hi;
                *(uint32_t*)&sAl[sbase + 2 * p] = lo;
            }
            float fb[16];
            if (kk0 < Kact) {
#pragma unroll
                for (int q = 0; q < 4; q++) {
                    float4 v = *(const float4*)&B[brow + kk0 + q * 4];
                    fb[q * 4] = v.x; fb[q * 4 + 1] = v.y;
                    fb[q * 4 + 2] = v.z; fb[q * 4 + 3] = v.w;
                }
            } else {
#pragma unroll
                for (int e = 0; e < 16; e++) fb[e] = 0.f;
            }
#pragma unroll
            for (int p = 0; p < 8; p++) {
                uint32_t lo;
                uint32_t hi = pack_bf16_hi(fb[2 * p], fb[2 * p + 1], lo);
                *(uint32_t*)&sBh[sbase + 2 * p] = hi;
                *(uint32_t*)&sBl[sbase + 2 * p] = lo;
            }
        }
        __syncthreads();

#pragma unroll
        for (int k16 = 0; k16 < 2; k16++) {
            const int kb = k16 * 16 + 2 * tig;
            uint32_t ah[2][4], al[2][4];
#pragma unroll
            for (int mt = 0; mt < 2; mt++) {
                int r0 = (mw + mt * 16 + g) * SMS;
                int r1 = r0 + 8 * SMS;
                ah[mt][0] = *(uint32_t*)&sAh[r0 + kb];
                ah[mt][1] = *(uint32_t*)&sAh[r1 + kb];
                ah[mt][2] = *(uint32_t*)&sAh[r0 + kb + 8];
                ah[mt][3] = *(uint32_t*)&sAh[r1 + kb + 8];
                al[mt][0] = *(uint32_t*)&sAl[r0 + kb];
                al[mt][1] = *(uint32_t*)&sAl[r1 + kb];
                al[mt][2] = *(uint32_t*)&sAl[r0 + kb + 8];
                al[mt][3] = *(uint32_t*)&sAl[r1 + kb + 8];
            }
#pragma unroll
            for (int nt = 0; nt < 8; nt++) {
                int rn = (nw + nt * 8 + g) * SMS;
                uint32_t bh[2], bl[2];
                bh[0] = *(uint32_t*)&sBh[rn + kb];
                bh[1] = *(uint32_t*)&sBh[rn + kb + 8];
                bl[0] = *(uint32_t*)&sBl[rn + kb];
                bl[1] = *(uint32_t*)&sBl[rn + kb + 8];
#pragma unroll
                for (int mt = 0; mt < 2; mt++) {
                    mma16816(acc[mt][nt], ah[mt], bh);
                    mma16816(acc[mt][nt], al[mt], bh);
                    mma16816(acc[mt][nt], ah[mt], bl);
                }
            }
        }
    }

    // epilogue
#pragma unroll
    for (int mt = 0; mt < 2; mt++) {
        int mrow0 = m0 + mw + mt * 16 + g;
#pragma unroll
        for (int half = 0; half < 2; half++) {
            int m = mrow0 + half * 8;
            if (m >= M) continue;
            size_t cro = (size_t)m * ldc;
#pragma unroll
            for (int nt = 0; nt < 8; nt++) {
                int n = n0 + nw + nt * 8 + 2 * tig;
                float v0 = acc[mt][nt][half * 2];
                float v1 = acc[mt][nt][half * 2 + 1];
                if (bias) {
                    float2 bb = *(const float2*)&bias[n];
                    v0 += bb.x; v1 += bb.y;
                }
                if (Cadd) {
                    float2 ca = *(const float2*)&Cadd[cro + n];
                    v0 += ca.x; v1 += ca.y;
                }
                *(float2*)&C[cro + n] = make_float2(v0, v1);
            }
        }
    }
}

// ---------------- tiny prep kernels ------------------------------------------
__global__ void k_prep0(const float* __restrict__ gcn_w, const float* __restrict__ gcn_wb,
                        const float* __restrict__ gcn_b, const float* __restrict__ hop_gate,
                        const float* __restrict__ attn_w) {
    int t = threadIdx.x;  // 128
    if (t == 0) {
        float a = hop_gate[0], b = hop_gate[1];
        float m = fmaxf(a, b);
        float ea = expf(a - m), eb = expf(b - m);
        g_gw[0] = ea / (ea + eb);
        g_gw[1] = eb / (ea + eb);
    }
    if (t < 128) {
        g_biasvec[t] = gcn_wb[t] + gcn_b[t];
        float ur = 0.f, ue = 0.f;
        for (int d = 0; d < 128; d++) {
            float aw = attn_w[d];
            ur += gcn_w[d * 256 + t] * aw;
            ue += gcn_w[d * 256 + 128 + t] * aw;
        }
        g_u[t] = ur;
        g_u[128 + t] = ue;
    }
}

__global__ void k_prepB(const float* __restrict__ w_ih, const float* __restrict__ w_hh,
                        const float* __restrict__ b_ih, const float* __restrict__ b_hh) {
    int n = blockIdx.x;   // 1024
    int t = threadIdx.x;  // 256
    int src = ((n >> 8) << 9) + (n & 255);
    g_WihN[n * 256 + t]   = w_ih[src * 256 + t];
    g_WstepN[n * 272 + t] = w_hh[src * 512 + t];
    if (t < 11) g_WstepN[n * 272 + 261 + t] = 0.f;
    if (t == 0) g_bias2[n] = b_ih[src] + b_hh[src];
}

// ---------------- per-symbol score scalars ------------------------------------
__global__ void k_scal(const float* __restrict__ emb) {
    __shared__ float su[256];
    int t = threadIdx.x;
    su[t] = g_u[t];
    __syncthreads();
    int warp = t >> 5, lane = t & 31;
    int s = blockIdx.x * 8 + warp;
    if (s >= NSYM) return;
    float pr = 0.f, pe = 0.f;
#pragma unroll
    for (int i = 0; i < 4; i++) {
        int k = lane + i * 32;
        float e = emb[(size_t)s * 128 + k];
        pr += e * su[k];
        pe += e * su[128 + k];
    }
#pragma unroll
    for (int o = 16; o; o >>= 1) {
        pr += __shfl_down_sync(0xffffffffu, pr, o);
        pe += __shfl_down_sync(0xffffffffu, pe, o);
    }
    if (lane == 0) g_scal[s] = make_float2(pr, pe);
}

// ---------------- neighbor encoder: softmax + weighted embedding sums ----------
__global__ __launch_bounds__(512) void k_neigh(
    const int* __restrict__ c0, const int* __restrict__ c1,
    const int* __restrict__ c2, const int* __restrict__ c3,
    const float* __restrict__ emb, int rowbase) {
    __shared__ int   s_idx[4][NN_][2];
    __shared__ float s_e[4][NN_];
    const int n = blockIdx.x;
    const int t = threadIdx.x;
    const int g = t >> 7, r = t & 127;
    const int* cp = (g == 0) ? c0 : (g == 1) ? c1 : (g == 2) ? c2 : c3;
    {
        int j = r >> 1, w = r & 1;
        s_idx[g][j][w] = cp[((size_t)n * NN_ + j) * 2 + w];
    }
    __syncthreads();
    if (r < NN_) {
        float2 sr = g_scal[s_idx[g][r][0]];
        float2 se = g_scal[s_idx[g][r][1]];
        s_e[g][r] = sr.x + se.y;
    }
    __syncthreads();
    float mx = -1e30f;
#pragma unroll 8
    for (int j = 0; j < NN_; j++) mx = fmaxf(mx, s_e[g][j]);
    __syncthreads();
    if (r < NN_) s_e[g][r] = expf(s_e[g][r] - mx);
    __syncthreads();
    float sum = 0.f;
#pragma unroll 8
    for (int j = 0; j < NN_; j++) sum += s_e[g][j];
    float inv = 1.f / sum;

    float accR = 0.f, accE = 0.f;
#pragma unroll 4
    for (int j = 0; j < NN_; j++) {
        float w = s_e[g][j] * inv;
        accR += w * __ldg(&emb[(size_t)s_idx[g][j][0] * 128 + r]);
        accE += w * __ldg(&emb[(size_t)s_idx[g][j][1] * 128 + r]);
    }
    size_t yrow = (size_t)(rowbase + n * 4 + g) * 256;
    g_Y[yrow + r]       = accR;
    g_Y[yrow + 128 + r] = accE;
}

// ---------------- combine: tanh + hop-gate mix ---------------------------------
__global__ void k_mix(float* __restrict__ out, int rowbase) {
    int n = blockIdx.x, t = threadIdx.x;  // 256
    int side = t >> 7, d = t & 127;
    size_t r0 = (size_t)(rowbase + n * 4 + side * 2) * 128;
    float v = g_gw[0] * tanhf(g_P[r0 + d]) + g_gw[1] * tanhf(g_P[r0 + 128 + d]);
    out[(size_t)n * 256 + t] = v;
}

// ---------------- support encoder chain ----------------------------------------
__device__ __forceinline__ float warp_sum(float v) {
#pragma unroll
    for (int o = 16; o; o >>= 1) v += __shfl_down_sync(0xffffffffu, v, o);
    return v;
}

__global__ void k_sup1(const float* __restrict__ p1_w, const float* __restrict__ p1_b) {
    int warp = threadIdx.x >> 5, lane = threadIdx.x & 31;
    int gw = blockIdx.x * 8 + warp;
    if (gw >= FEW * DI) return;
    int f = gw / DI, j = gw - f * DI;
    float s = 0.f;
#pragma unroll
    for (int i = 0; i < 8; i++) {
        int k = lane + i * 32;
        s += g_sn[f * DM + k] * p1_w[j * DM + k];
    }
    s = warp_sum(s);
    if (lane == 0) g_h1[f * DI + j] = fmaxf(s + p1_b[j], 0.f);
}

__global__ void k_sup2(const float* __restrict__ p2_w, const float* __restrict__ p2_b) {
    int warp = threadIdx.x >> 5, lane = threadIdx.x & 31;
    int gw = blockIdx.x * 8 + warp;
    if (gw >= FEW * DM) return;
    int f = gw / DM, d = gw - f * DM;
    float s = 0.f;
#pragma unroll
    for (int i = 0; i < 16; i++) {
        int k = lane + i * 32;
        s += g_h1[f * DI + k] * p2_w[d * DI + k];
    }
    s = warp_sum(s);
    if (lane == 0) g_z[f * DM + d] = s + p2_b[d] + g_sn[f * DM + d];
}

__global__ void k_ln(const float* __restrict__ ln_g, const float* __restrict__ ln_b) {
    __shared__ float sred[8];
    int f = blockIdx.x, t = threadIdx.x;  // 256
    float z = g_z[f * DM + t];
    int lane = t & 31, warp = t >> 5;

    float v = warp_sum(z);
    if (lane == 0) sred[warp] = v;
    __syncthreads();
    if (t == 0) {
        float s = 0.f;
        for (int w = 0; w < 8; w++) s += sred[w];
        sred[0] = s * (1.f / 256.f);
    }
    __syncthreads();
    float mu = sred[0];
    __syncthreads();
    float dv = z - mu;
    float v2 = warp_sum(dv * dv);
    if (lane == 0) sred[warp] = v2;
    __syncthreads();
    if (t == 0) {
        float s = 0.f;
        for (int w = 0; w < 8; w++) s += sred[w];
        sred[0] = s * (1.f / 256.f);
    }
    __syncthreads();
    float var = sred[0];
    g_sg[f * DM + t] = dv * rsqrtf(var + 1e-6f) * ln_g[t] + ln_b[t];
}

__global__ void k_sm_mean() {
    int t = threadIdx.x;  // 256
    float s = 0.f;
#pragma unroll
    for (int f = 0; f < FEW; f++) s += g_sg[f * DM + t];
    g_sm[t] = s * (1.f / (float)FEW);
}

__global__ void k_sgw(const float* __restrict__ w_hh) {
    int warp = threadIdx.x >> 5, lane = threadIdx.x & 31;
    int gw = blockIdx.x * 8 + warp;
    if (gw >= FEW * G1K) return;
    int f = gw / G1K, n = gw - f * G1K;
    int src = ((n >> 8) << 9) + (n & 255);
    float s = 0.f;
#pragma unroll
    for (int i = 0; i < 8; i++) {
        int k = lane + i * 32;
        s += g_sg[f * DM + k] * w_hh[src * 512 + 256 + k];
    }
    s = warp_sum(s);
    if (lane == 0) g_WstepN[n * 272 + 256 + f] = s;
}

// ---------------- fused LSTM cell + h update + attn softmax -------------------
__global__ __launch_bounds__(256) void k_lstm(const float* __restrict__ gates,
                                              int first, int last,
                                              float* __restrict__ out) {
    __shared__ float red[8][5];
    const int b = blockIdx.x, t = threadIdx.x;
    const float* gr = gates + (size_t)b * G1K;
    float gi = gr[t], gf = gr[256 + t], gg = gr[512 + t], go = gr[768 + t];
    float cold = first ? 0.f : g_c[(size_t)b * 256 + t];
    float cn = sigf(gf) * cold + sigf(gi) * tanhf(gg);
    float hc = sigf(go) * tanhf(cn);
    g_c[(size_t)b * 256 + t] = cn;
    float hv = g_qn[(size_t)b * 256 + t] + hc;
    g_X[(size_t)b * KX + t] = hv;
    if (first && t < (KX - 261)) g_X[(size_t)b * KX + 261 + t] = 0.f;

    int lane = t & 31, warp = t >> 5;
    if (last) {
        float p = warp_sum(hv * g_sm[t]);
        if (lane == 0) red[warp][0] = p;
        __syncthreads();
        if (t == 0) {
            float s = 0.f;
            for (int w = 0; w < 8; w++) s += red[w][0];
            out[b] = s;
        }
    } else {
        float p[FEW];
#pragma unroll
        for (int f = 0; f < FEW; f++) p[f] = warp_sum(hv * g_sg[f * DM + t]);
        if (lane == 0)
#pragma unroll
            for (int f = 0; f < FEW; f++) red[warp][f] = p[f];
        __syncthreads();
        if (t == 0) {
            float s[FEW];
#pragma unroll
            for (int f = 0; f < FEW; f++) {
                float acc = 0.f;
                for (int w = 0; w < 8; w++) acc += red[w][f];
                s[f] = acc;
            }
            float m = s[0];
#pragma unroll
            for (int f = 1; f < FEW; f++) m = fmaxf(m, s[f]);
            float e[FEW], se = 0.f;
#pragma unroll
            for (int f = 0; f < FEW; f++) { e[f] = expf(s[f] - m); se += e[f]; }
            float inv = 1.f / se;
#pragma unroll
            for (int f = 0; f < FEW; f++) g_X[(size_t)b * KX + 256 + f] = e[f] * inv;
        }
    }
}

// ---------------- host launcher ------------------------------------------------
template <typename T>
static float* symaddr(T& sym) {
    void* p = nullptr;
    cudaGetSymbolAddress(&p, sym);
    return (float*)p;
}

extern "C" void kernel_launch(void* const* d_in, const int* in_sizes, int n_in,
                              void* d_out, int out_size) {
    const int* q_l1 = (const int*)d_in[0];
    const int* q_l2 = (const int*)d_in[1];
    const int* q_r1 = (const int*)d_in[2];
    const int* q_r2 = (const int*)d_in[3];
    const int* s_l1 = (const int*)d_in[4];
    const int* s_l2 = (const int*)d_in[5];
    const int* s_r1 = (const int*)d_in[6];
    const int* s_r2 = (const int*)d_in[7];
    const float* emb      = (const float*)d_in[12];
    const float* gcn_w    = (const float*)d_in[13];
    const float* gcn_wb   = (const float*)d_in[14];
    const float* gcn_b    = (const float*)d_in[15];
    const float* hop_gate = (const float*)d_in[16];
    const float* attn_w   = (const float*)d_in[17];
    const float* p1_w = (const float*)d_in[19];
    const float* p1_b = (const float*)d_in[20];
    const float* p2_w = (const float*)d_in[21];
    const float* p2_b = (const float*)d_in[22];
    const float* ln_g = (const float*)d_in[23];
    const float* ln_b = (const float*)d_in[24];
    const float* w_ih = (const float*)d_in[25];
    const float* w_hh = (const float*)d_in[26];
    const float* b_ih = (const float*)d_in[27];
    const float* b_hh = (const float*)d_in[28];
    float* out = (float*)d_out;

    float* pY     = symaddr(g_Y);
    float* pP     = symaddr(g_P);
    float* pQn    = symaddr(g_qn);
    float* pSn    = symaddr(g_sn);
    float* pWihN  = symaddr(g_WihN);
    float* pWstepN= symaddr(g_WstepN);
    float* pBias2 = symaddr(g_bias2);
    float* pBiasV = symaddr(g_biasvec);
    float* pA     = symaddr(g_A);
    float* pG     = symaddr(g_G);
    float* pX     = symaddr(g_X);

    // prep
    k_prep0<<<1, 128>>>(gcn_w, gcn_wb, gcn_b, hop_gate, attn_w);
    k_prepB<<<1024, 256>>>(w_ih, w_hh, b_ih, b_hh);
    k_scal<<<NSYM / 8, 256>>>(emb);

    // neighbor encoders: weighted embedding sums into Y
    k_neigh<<<B_, 512>>>(q_l1, q_l2, q_r1, q_r2, emb, 0);
    k_neigh<<<FEW, 512>>>(s_l1, s_l2, s_r1, s_r2, emb, B_ * 4);

    // P = Y @ gcn_w^T + biasvec   [16404,256]@[256,128]
    gemm_tc<<<dim3((YROWS + 127) / 128, 1), 256>>>(
        pY, 256, YROWS, gcn_w, 256, pP, 128, nullptr, pBiasV, 256, 8);

    // tanh + hop-gate mix
    k_mix<<<B_, 256>>>(pQn, 0);
    k_mix<<<FEW, 256>>>(pSn, B_ * 4);

    // support encoder
    k_sup1<<<(FEW * DI) / 8, 256>>>(p1_w, p1_b);
    k_sup2<<<(FEW * DM) / 8, 256>>>(p2_w, p2_b);
    k_ln<<<FEW, 256>>>(ln_g, ln_b);
    k_sm_mean<<<1, 256>>>();
    k_sgw<<<(FEW * G1K + 7) / 8, 256>>>(w_hh);

    // A = qn @ w_ihN^T + (b_ih + b_hh)   [4096,256]@[256,1024]
    gemm_tc<<<dim3(B_ / 128, G1K / 128), 256>>>(
        pQn, 256, B_, pWihN, 256, pA, G1K, nullptr, pBias2, 256, 8);

    // step 1: gates = A (h_r = 0)
    k_lstm<<<B_, 256>>>(pA, 1, 0, out);

    // steps 2..4: G = A + [h|attn|0] @ WstepN^T   [4096,272]@[272,1024]
    for (int s = 2; s <= 4; s++) {
        gemm_tc<<<dim3(B_ / 128, G1K / 128), 256>>>(
            pX, KX, B_, pWstepN, KX, pG, G1K, pA, nullptr, KX, 9);
        k_lstm<<<B_, 256>>>(pG, 0, (s == 4) ? 1 : 0, out);
    }
}

// round 6
// speedup vs baseline: 2.6477x; 1.1633x over previous
#include <cuda_runtime.h>
#include <cuda_bf16.h>
#include <cuda_fp16.h>
#include <math.h>
#include <stdint.h>

#define B_    4096
#define FEW   5
#define NN_   64
#define NSYM  100000
#define DM    256
#define DI    512
#define G1K   1024
#define KX    272
#define YROWS (B_ * 4 + FEW * 4)   // 16404

// ---------------- scratch (static device globals; no allocation) -------------
__device__ float2 g_scal[NSYM];
__device__ __half g_embh[(size_t)NSYM * 128];   // fp16 copy of emb for gathers
__device__ float  g_u[2 * 128];
__device__ float  g_gw[2];
__device__ float  g_biasvec[128];
__device__ float  g_Y[(size_t)(YROWS + 12) * 256];
__device__ float  g_P[(size_t)(YROWS + 12) * 128];
__device__ float  g_qn[(size_t)B_ * DM];
__device__ float  g_sn[FEW * DM];
__device__ float  g_h1[FEW * DI];
__device__ float  g_z[FEW * DM];
__device__ float  g_sg[FEW * DM];
__device__ float  g_sm[DM];
__device__ float  g_WihN[1024 * 256];
__device__ float  g_WstepN[1024 * 272];
__device__ float  g_bias2[G1K];
__device__ float  g_A[(size_t)B_ * G1K];
__device__ float  g_G[(size_t)B_ * G1K];
__device__ float  g_X[(size_t)B_ * KX];
__device__ float  g_c[(size_t)B_ * 256];

__device__ __forceinline__ float sigfast(float x) {
    return __fdividef(1.f, 1.f + __expf(-x));
}
__device__ __forceinline__ float tanhfast(float x) {
    float t = __expf(2.f * x);
    return 1.f - __fdividef(2.f, t + 1.f);
}

// ---------------- mma.sync bf16x3 GEMM (unchanged from R5, passing) ----------
#define KC 32
#define SMS 40

__device__ __forceinline__ uint32_t pack_bf16_hi(float x, float y,
                                                 uint32_t& lo_out) {
    __nv_bfloat16 hx = __float2bfloat16(x);
    __nv_bfloat16 hy = __float2bfloat16(y);
    float rx = x - __bfloat162float(hx);
    float ry = y - __bfloat162float(hy);
    __nv_bfloat16 lx = __float2bfloat16(rx);
    __nv_bfloat16 ly = __float2bfloat16(ry);
    uint32_t hi = (uint32_t)*(uint16_t*)&hx | ((uint32_t)*(uint16_t*)&hy << 16);
    lo_out = (uint32_t)*(uint16_t*)&lx | ((uint32_t)*(uint16_t*)&ly << 16);
    return hi;
}

__device__ __forceinline__ void mma16816(float* d, const uint32_t* a,
                                         const uint32_t* b) {
    asm volatile(
        "mma.sync.aligned.m16n8k16.row.col.f32.bf16.bf16.f32 "
        "{%0,%1,%2,%3}, {%4,%5,%6,%7}, {%8,%9}, {%0,%1,%2,%3};"
        : "+f"(d[0]), "+f"(d[1]), "+f"(d[2]), "+f"(d[3])
        : "r"(a[0]), "r"(a[1]), "r"(a[2]), "r"(a[3]), "r"(b[0]), "r"(b[1]));
}

__global__ __launch_bounds__(256, 2) void gemm_tc(
    const float* __restrict__ A, int lda, int M,
    const float* __restrict__ B, int ldb,
    float* __restrict__ C, int ldc,
    const float* __restrict__ Cadd, const float* __restrict__ bias,
    int Kact, int NC) {
    __shared__ uint16_t sAh[128 * SMS];
    __shared__ uint16_t sAl[128 * SMS];
    __shared__ uint16_t sBh[128 * SMS];
    __shared__ uint16_t sBl[128 * SMS];

    const int t = threadIdx.x;
    const int w = t >> 5, lane = t & 31;
    const int g = lane >> 2, tig = lane & 3;
    const int m0 = blockIdx.x * 128, n0 = blockIdx.y * 128;
    const int mw = (w & 3) * 32;
    const int nw = (w >> 2) * 64;

    float acc[2][8][4];
#pragma unroll
    for (int mt = 0; mt < 2; mt++)
#pragma unroll
        for (int nt = 0; nt < 8; nt++)
#pragma unroll
            for (int e = 0; e < 4; e++) acc[mt][nt][e] = 0.f;

    const int lrow = t >> 1;
    const int lhalf = (t & 1) * 16;
    const bool mok = (m0 + lrow) < M;
    const size_t arow = (size_t)(m0 + lrow) * lda;
    const size_t brow = (size_t)(n0 + lrow) * ldb;
    const int sbase = lrow * SMS + lhalf;

    for (int c = 0; c < NC; c++) {
        const int kk0 = c * KC + lhalf;
        __syncthreads();
        {
            float fa[16];
            if (mok && kk0 < Kact) {
#pragma unroll
                for (int q = 0; q < 4; q++) {
                    float4 v = *(const float4*)&A[arow + kk0 + q * 4];
                    fa[q * 4] = v.x; fa[q * 4 + 1] = v.y;
                    fa[q * 4 + 2] = v.z; fa[q * 4 + 3] = v.w;
                }
            } else {
#pragma unroll
                for (int e = 0; e < 16; e++) fa[e] = 0.f;
            }
#pragma unroll
            for (int p = 0; p < 8; p++) {
                uint32_t lo;
                uint32_t hi = pack_bf16_hi(fa[2 * p], fa[2 * p + 1], lo);
                *(uint32_t*)&sAh[sbase + 2 * p] = hi;
                *(uint32_t*)&sAl[sbase + 2 * p] = lo;
            }
            float fb[16];
            if (kk0 < Kact) {
#pragma unroll
                for (int q = 0; q < 4; q++) {
                    float4 v = *(const float4*)&B[brow + kk0 + q * 4];
                    fb[q * 4] = v.x; fb[q * 4 + 1] = v.y;
                    fb[q * 4 + 2] = v.z; fb[q * 4 + 3] = v.w;
                }
            } else {
#pragma unroll
                for (int e = 0; e < 16; e++) fb[e] = 0.f;
            }
#pragma unroll
            for (int p = 0; p < 8; p++) {
                uint32_t lo;
                uint32_t hi = pack_bf16_hi(fb[2 * p], fb[2 * p + 1], lo);
                *(uint32_t*)&sBh[sbase + 2 * p] = hi;
                *(uint32_t*)&sBl[sbase + 2 * p] = lo;
            }
        }
        __syncthreads();

#pragma unroll
        for (int k16 = 0; k16 < 2; k16++) {
            const int kb = k16 * 16 + 2 * tig;
            uint32_t ah[2][4], al[2][4];
#pragma unroll
            for (int mt = 0; mt < 2; mt++) {
                int r0 = (mw + mt * 16 + g) * SMS;
                int r1 = r0 + 8 * SMS;
                ah[mt][0] = *(uint32_t*)&sAh[r0 + kb];
                ah[mt][1] = *(uint32_t*)&sAh[r1 + kb];
                ah[mt][2] = *(uint32_t*)&sAh[r0 + kb + 8];
                ah[mt][3] = *(uint32_t*)&sAh[r1 + kb + 8];
                al[mt][0] = *(uint32_t*)&sAl[r0 + kb];
                al[mt][1] = *(uint32_t*)&sAl[r1 + kb];
                al[mt][2] = *(uint32_t*)&sAl[r0 + kb + 8];
                al[mt][3] = *(uint32_t*)&sAl[r1 + kb + 8];
            }
#pragma unroll
            for (int nt = 0; nt < 8; nt++) {
                int rn = (nw + nt * 8 + g) * SMS;
                uint32_t bh[2], bl[2];
                bh[0] = *(uint32_t*)&sBh[rn + kb];
                bh[1] = *(uint32_t*)&sBh[rn + kb + 8];
                bl[0] = *(uint32_t*)&sBl[rn + kb];
                bl[1] = *(uint32_t*)&sBl[rn + kb + 8];
#pragma unroll
                for (int mt = 0; mt < 2; mt++) {
                    mma16816(acc[mt][nt], ah[mt], bh);
                    mma16816(acc[mt][nt], al[mt], bh);
                    mma16816(acc[mt][nt], ah[mt], bl);
                }
            }
        }
    }

#pragma unroll
    for (int mt = 0; mt < 2; mt++) {
        int mrow0 = m0 + mw + mt * 16 + g;
#pragma unroll
        for (int half = 0; half < 2; half++) {
            int m = mrow0 + half * 8;
            if (m >= M) continue;
            size_t cro = (size_t)m * ldc;
#pragma unroll
            for (int nt = 0; nt < 8; nt++) {
                int n = n0 + nw + nt * 8 + 2 * tig;
                float v0 = acc[mt][nt][half * 2];
                float v1 = acc[mt][nt][half * 2 + 1];
                if (bias) {
                    float2 bb = *(const float2*)&bias[n];
                    v0 += bb.x; v1 += bb.y;
                }
                if (Cadd) {
                    float2 ca = *(const float2*)&Cadd[cro + n];
                    v0 += ca.x; v1 += ca.y;
                }
                *(float2*)&C[cro + n] = make_float2(v0, v1);
            }
        }
    }
}

// ---------------- tiny prep kernels ------------------------------------------
__global__ void k_prep0(const float* __restrict__ gcn_w, const float* __restrict__ gcn_wb,
                        const float* __restrict__ gcn_b, const float* __restrict__ hop_gate,
                        const float* __restrict__ attn_w) {
    int t = threadIdx.x;  // 128
    if (t == 0) {
        float a = hop_gate[0], b = hop_gate[1];
        float m = fmaxf(a, b);
        float ea = expf(a - m), eb = expf(b - m);
        g_gw[0] = ea / (ea + eb);
        g_gw[1] = eb / (ea + eb);
    }
    if (t < 128) {
        g_biasvec[t] = gcn_wb[t] + gcn_b[t];
        float ur = 0.f, ue = 0.f;
        for (int d = 0; d < 128; d++) {
            float aw = attn_w[d];
            ur += gcn_w[d * 256 + t] * aw;
            ue += gcn_w[d * 256 + 128 + t] * aw;
        }
        g_u[t] = ur;
        g_u[128 + t] = ue;
    }
}

__global__ void k_prepB(const float* __restrict__ w_ih, const float* __restrict__ w_hh,
                        const float* __restrict__ b_ih, const float* __restrict__ b_hh) {
    int n = blockIdx.x;   // 1024
    int t = threadIdx.x;  // 256
    int src = ((n >> 8) << 9) + (n & 255);
    g_WihN[n * 256 + t]   = w_ih[src * 256 + t];
    g_WstepN[n * 272 + t] = w_hh[src * 512 + t];
    if (t < 11) g_WstepN[n * 272 + 261 + t] = 0.f;
    if (t == 0) g_bias2[n] = b_ih[src] + b_hh[src];
}

// ---------------- per-symbol score scalars + fp16 table ------------------------
__global__ __launch_bounds__(256) void k_scal(const float* __restrict__ emb) {
    __shared__ float su[256];
    int t = threadIdx.x;
    su[t] = g_u[t];
    __syncthreads();
    int warp = t >> 5, lane = t & 31;
    int s = blockIdx.x * 8 + warp;
    if (s >= NSYM) return;
    float4 e = *(const float4*)&emb[(size_t)s * 128 + lane * 4];
    float4 ur = ((const float4*)su)[lane];
    float4 ue = ((const float4*)(su + 128))[lane];
    float pr = e.x * ur.x + e.y * ur.y + e.z * ur.z + e.w * ur.w;
    float pe = e.x * ue.x + e.y * ue.y + e.z * ue.z + e.w * ue.w;
#pragma unroll
    for (int o = 16; o; o >>= 1) {
        pr += __shfl_xor_sync(0xffffffffu, pr, o);
        pe += __shfl_xor_sync(0xffffffffu, pe, o);
    }
    if (lane == 0) g_scal[s] = make_float2(pr, pe);
    // emit fp16 copy
    __half2 h0 = __float22half2_rn(make_float2(e.x, e.y));
    __half2 h1 = __float22half2_rn(make_float2(e.z, e.w));
    uint2 pk;
    pk.x = *(uint32_t*)&h0;
    pk.y = *(uint32_t*)&h1;
    ((uint2*)g_embh)[(size_t)s * 32 + lane] = pk;
}

// ---------------- neighbor encoder v2: warp per (n, hop) -----------------------
__global__ __launch_bounds__(512) void k_neigh(
    const int* __restrict__ c0, const int* __restrict__ c1,
    const int* __restrict__ c2, const int* __restrict__ c3,
    int rowbase, int ncount) {
    __shared__ int4 smeta[16][64];
    const int t = threadIdx.x;
    const int w = t >> 5, lane = t & 31;
    const int g = w & 3;
    const int nb = blockIdx.x * 4 + (w >> 2);
    if (nb >= ncount) return;
    const int* cp = (g == 0) ? c0 : (g == 1) ? c1 : (g == 2) ? c2 : c3;

    int2 p0 = ((const int2*)cp)[(size_t)nb * NN_ + lane];
    int2 p1 = ((const int2*)cp)[(size_t)nb * NN_ + 32 + lane];
    float2 s0r = g_scal[p0.x], s0e = g_scal[p0.y];
    float2 s1r = g_scal[p1.x], s1e = g_scal[p1.y];
    float e0 = s0r.x + s0e.y;
    float e1 = s1r.x + s1e.y;
    float m = fmaxf(e0, e1);
#pragma unroll
    for (int o = 16; o; o >>= 1) m = fmaxf(m, __shfl_xor_sync(0xffffffffu, m, o));
    float w0 = __expf(e0 - m), w1 = __expf(e1 - m);
    float s = w0 + w1;
#pragma unroll
    for (int o = 16; o; o >>= 1) s += __shfl_xor_sync(0xffffffffu, s, o);
    float inv = __fdividef(1.f, s);

    smeta[w][lane]      = make_int4(p0.x, p0.y, __float_as_int(w0), 0);
    smeta[w][lane + 32] = make_int4(p1.x, p1.y, __float_as_int(w1), 0);
    __syncwarp();

    const uint2* e2 = (const uint2*)g_embh;  // 4 halves per entry; row = 32 entries
    float4 accR = make_float4(0.f, 0.f, 0.f, 0.f);
    float4 accE = make_float4(0.f, 0.f, 0.f, 0.f);
#pragma unroll 4
    for (int j = 0; j < NN_; j++) {
        int4 mt = smeta[w][j];
        float wj = __int_as_float(mt.z);
        uint2 vr = __ldg(&e2[(size_t)mt.x * 32 + lane]);
        uint2 ve = __ldg(&e2[(size_t)mt.y * 32 + lane]);
        float2 r01 = __half22float2(*(__half2*)&vr.x);
        float2 r23 = __half22float2(*(__half2*)&vr.y);
        float2 q01 = __half22float2(*(__half2*)&ve.x);
        float2 q23 = __half22float2(*(__half2*)&ve.y);
        accR.x += wj * r01.x; accR.y += wj * r01.y;
        accR.z += wj * r23.x; accR.w += wj * r23.y;
        accE.x += wj * q01.x; accE.y += wj * q01.y;
        accE.z += wj * q23.x; accE.w += wj * q23.y;
    }
    accR.x *= inv; accR.y *= inv; accR.z *= inv; accR.w *= inv;
    accE.x *= inv; accE.y *= inv; accE.z *= inv; accE.w *= inv;

    size_t yrow = (size_t)(rowbase + nb * 4 + g) * 256;
    *(float4*)&g_Y[yrow + 4 * lane]       = accR;
    *(float4*)&g_Y[yrow + 128 + 4 * lane] = accE;
}

// ---------------- combine: tanh + hop-gate mix ---------------------------------
__global__ void k_mix(float* __restrict__ out, int rowbase) {
    int n = blockIdx.x, t = threadIdx.x;  // 256
    int side = t >> 7, d = t & 127;
    size_t r0 = (size_t)(rowbase + n * 4 + side * 2) * 128;
    float v = g_gw[0] * tanhfast(g_P[r0 + d]) + g_gw[1] * tanhfast(g_P[r0 + 128 + d]);
    out[(size_t)n * 256 + t] = v;
}

// ---------------- support encoder chain ----------------------------------------
__device__ __forceinline__ float warp_sum(float v) {
#pragma unroll
    for (int o = 16; o; o >>= 1) v += __shfl_down_sync(0xffffffffu, v, o);
    return v;
}

__global__ void k_sup1(const float* __restrict__ p1_w, const float* __restrict__ p1_b) {
    int warp = threadIdx.x >> 5, lane = threadIdx.x & 31;
    int gw = blockIdx.x * 8 + warp;
    if (gw >= FEW * DI) return;
    int f = gw / DI, j = gw - f * DI;
    float s = 0.f;
#pragma unroll
    for (int i = 0; i < 8; i++) {
        int k = lane + i * 32;
        s += g_sn[f * DM + k] * p1_w[j * DM + k];
    }
    s = warp_sum(s);
    if (lane == 0) g_h1[f * DI + j] = fmaxf(s + p1_b[j], 0.f);
}

__global__ void k_sup2(const float* __restrict__ p2_w, const float* __restrict__ p2_b) {
    int warp = threadIdx.x >> 5, lane = threadIdx.x & 31;
    int gw = blockIdx.x * 8 + warp;
    if (gw >= FEW * DM) return;
    int f = gw / DM, d = gw - f * DM;
    float s = 0.f;
#pragma unroll
    for (int i = 0; i < 16; i++) {
        int k = lane + i * 32;
        s += g_h1[f * DI + k] * p2_w[d * DI + k];
    }
    s = warp_sum(s);
    if (lane == 0) g_z[f * DM + d] = s + p2_b[d] + g_sn[f * DM + d];
}

// LN for all FEW rows + support mean, single block of 256
__global__ void k_lnmean(const float* __restrict__ ln_g, const float* __restrict__ ln_b) {
    __shared__ float sred[8];
    int t = threadIdx.x;
    int lane = t & 31, warp = t >> 5;
    float gg = ln_g[t], bb = ln_b[t];
    float msum = 0.f;
    for (int f = 0; f < FEW; f++) {
        float z = g_z[f * DM + t];
        float v = warp_sum(z);
        if (lane == 0) sred[warp] = v;
        __syncthreads();
        if (t == 0) {
            float s = 0.f;
            for (int w = 0; w < 8; w++) s += sred[w];
            sred[0] = s * (1.f / 256.f);
        }
        __syncthreads();
        float mu = sred[0];
        __syncthreads();
        float dv = z - mu;
        float v2 = warp_sum(dv * dv);
        if (lane == 0) sred[warp] = v2;
        __syncthreads();
        if (t == 0) {
            float s = 0.f;
            for (int w = 0; w < 8; w++) s += sred[w];
            sred[0] = s * (1.f / 256.f);
        }
        __syncthreads();
        float var = sred[0];
        __syncthreads();
        float o = dv * rsqrtf(var + 1e-6f) * gg + bb;
        g_sg[f * DM + t] = o;
        msum += o;
    }
    g_sm[t] = msum * (1.f / (float)FEW);
}

__global__ void k_sgw(const float* __restrict__ w_hh) {
    int warp = threadIdx.x >> 5, lane = threadIdx.x & 31;
    int gw = blockIdx.x * 8 + warp;
    if (gw >= FEW * G1K) return;
    int f = gw / G1K, n = gw - f * G1K;
    int src = ((n >> 8) << 9) + (n & 255);
    float s = 0.f;
#pragma unroll
    for (int i = 0; i < 8; i++) {
        int k = lane + i * 32;
        s += g_sg[f * DM + k] * w_hh[src * 512 + 256 + k];
    }
    s = warp_sum(s);
    if (lane == 0) g_WstepN[n * 272 + 256 + f] = s;
}

// ---------------- fused LSTM cell + h update + attn softmax -------------------
__global__ __launch_bounds__(256) void k_lstm(const float* __restrict__ gates,
                                              int first, int last,
                                              float* __restrict__ out) {
    __shared__ float red[8][5];
    const int b = blockIdx.x, t = threadIdx.x;
    const float* gr = gates + (size_t)b * G1K;
    float gi = gr[t], gf = gr[256 + t], gg = gr[512 + t], go = gr[768 + t];
    float cold = first ? 0.f : g_c[(size_t)b * 256 + t];
    float cn = sigfast(gf) * cold + sigfast(gi) * tanhfast(gg);
    float hc = sigfast(go) * tanhfast(cn);
    g_c[(size_t)b * 256 + t] = cn;
    float hv = g_qn[(size_t)b * 256 + t] + hc;
    g_X[(size_t)b * KX + t] = hv;
    if (first && t < (KX - 261)) g_X[(size_t)b * KX + 261 + t] = 0.f;

    int lane = t & 31, warp = t >> 5;
    if (last) {
        float p = warp_sum(hv * g_sm[t]);
        if (lane == 0) red[warp][0] = p;
        __syncthreads();
        if (t == 0) {
            float s = 0.f;
            for (int w = 0; w < 8; w++) s += red[w][0];
            out[b] = s;
        }
    } else {
        float p[FEW];
#pragma unroll
        for (int f = 0; f < FEW; f++) p[f] = warp_sum(hv * g_sg[f * DM + t]);
        if (lane == 0)
#pragma unroll
            for (int f = 0; f < FEW; f++) red[warp][f] = p[f];
        __syncthreads();
        if (t == 0) {
            float s[FEW];
#pragma unroll
            for (int f = 0; f < FEW; f++) {
                float acc = 0.f;
                for (int w = 0; w < 8; w++) acc += red[w][f];
                s[f] = acc;
            }
            float m = s[0];
#pragma unroll
            for (int f = 1; f < FEW; f++) m = fmaxf(m, s[f]);
            float e[FEW], se = 0.f;
#pragma unroll
            for (int f = 0; f < FEW; f++) { e[f] = __expf(s[f] - m); se += e[f]; }
            float inv = __fdividef(1.f, se);
#pragma unroll
            for (int f = 0; f < FEW; f++) g_X[(size_t)b * KX + 256 + f] = e[f] * inv;
        }
    }
}

// ---------------- host launcher ------------------------------------------------
template <typename T>
static float* symaddr(T& sym) {
    void* p = nullptr;
    cudaGetSymbolAddress(&p, sym);
    return (float*)p;
}

extern "C" void kernel_launch(void* const* d_in, const int* in_sizes, int n_in,
                              void* d_out, int out_size) {
    const int* q_l1 = (const int*)d_in[0];
    const int* q_l2 = (const int*)d_in[1];
    const int* q_r1 = (const int*)d_in[2];
    const int* q_r2 = (const int*)d_in[3];
    const int* s_l1 = (const int*)d_in[4];
    const int* s_l2 = (const int*)d_in[5];
    const int* s_r1 = (const int*)d_in[6];
    const int* s_r2 = (const int*)d_in[7];
    const float* emb      = (const float*)d_in[12];
    const float* gcn_w    = (const float*)d_in[13];
    const float* gcn_wb   = (const float*)d_in[14];
    const float* gcn_b    = (const float*)d_in[15];
    const float* hop_gate = (const float*)d_in[16];
    const float* attn_w   = (const float*)d_in[17];
    const float* p1_w = (const float*)d_in[19];
    const float* p1_b = (const float*)d_in[20];
    const float* p2_w = (const float*)d_in[21];
    const float* p2_b = (const float*)d_in[22];
    const float* ln_g = (const float*)d_in[23];
    const float* ln_b = (const float*)d_in[24];
    const float* w_ih = (const float*)d_in[25];
    const float* w_hh = (const float*)d_in[26];
    const float* b_ih = (const float*)d_in[27];
    const float* b_hh = (const float*)d_in[28];
    float* out = (float*)d_out;

    float* pY     = symaddr(g_Y);
    float* pP     = symaddr(g_P);
    float* pQn    = symaddr(g_qn);
    float* pSn    = symaddr(g_sn);
    float* pWihN  = symaddr(g_WihN);
    float* pWstepN= symaddr(g_WstepN);
    float* pBias2 = symaddr(g_bias2);
    float* pBiasV = symaddr(g_biasvec);
    float* pA     = symaddr(g_A);
    float* pG     = symaddr(g_G);
    float* pX     = symaddr(g_X);

    // prep
    k_prep0<<<1, 128>>>(gcn_w, gcn_wb, gcn_b, hop_gate, attn_w);
    k_prepB<<<1024, 256>>>(w_ih, w_hh, b_ih, b_hh);
    k_scal<<<(NSYM + 7) / 8, 256>>>(emb);

    // neighbor encoders: weighted fp16-embedding sums into Y
    k_neigh<<<B_ / 4, 512>>>(q_l1, q_l2, q_r1, q_r2, 0, B_);
    k_neigh<<<(FEW + 3) / 4, 512>>>(s_l1, s_l2, s_r1, s_r2, B_ * 4, FEW);

    // P = Y @ gcn_w^T + biasvec   [16404,256]@[256,128]
    gemm_tc<<<dim3((YROWS + 127) / 128, 1), 256>>>(
        pY, 256, YROWS, gcn_w, 256, pP, 128, nullptr, pBiasV, 256, 8);

    // tanh + hop-gate mix
    k_mix<<<B_, 256>>>(pQn, 0);
    k_mix<<<FEW, 256>>>(pSn, B_ * 4);

    // support encoder
    k_sup1<<<(FEW * DI) / 8, 256>>>(p1_w, p1_b);
    k_sup2<<<(FEW * DM) / 8, 256>>>(p2_w, p2_b);
    k_lnmean<<<1, 256>>>(ln_g, ln_b);
    k_sgw<<<(FEW * G1K + 7) / 8, 256>>>(w_hh);

    // A = qn @ w_ihN^T + (b_ih + b_hh)   [4096,256]@[256,1024]
    gemm_tc<<<dim3(B_ / 128, G1K / 128), 256>>>(
        pQn, 256, B_, pWihN, 256, pA, G1K, nullptr, pBias2, 256, 8);

    // step 1: gates = A (h_r = 0)
    k_lstm<<<B_, 256>>>(pA, 1, 0, out);

    // steps 2..4: G = A + [h|attn|0] @ WstepN^T   [4096,272]@[272,1024]
    for (int s = 2; s <= 4; s++) {
        gemm_tc<<<dim3(B_ / 128, G1K / 128), 256>>>(
            pX, KX, B_, pWstepN, KX, pG, G1K, pA, nullptr, KX, 9);
        k_lstm<<<B_, 256>>>(pG, 0, (s == 4) ? 1 : 0, out);
    }
}

// round 7
// speedup vs baseline: 2.8577x; 1.0793x over previous
#include <cuda_runtime.h>
#include <cuda_bf16.h>
#include <cuda_fp16.h>
#include <math.h>
#include <stdint.h>

#define B_    4096
#define FEW   5
#define NN_   64
#define NSYM  100000
#define DM    256
#define DI    512
#define G1K   1024
#define XS    288    // X row stride: 256 h + 5 attn + 27 zero pad (9 chunks of 32)
#define YROWS (B_ * 4 + FEW * 4)   // 16404
#define YPAD  16512                 // 129 * 128

// ---------------- scratch (static device globals; no allocation) -------------
__device__ float2   g_scal[NSYM];
__device__ __half   g_embh[(size_t)NSYM * 128];
__device__ float    g_u[2 * 128];
__device__ float    g_gw[2];
__device__ float    g_biasvec[128];
__device__ uint16_t g_Yhi[(size_t)YPAD * 256];
__device__ uint16_t g_Ylo[(size_t)YPAD * 256];
__device__ float    g_P[(size_t)YPAD * 128];
__device__ float    g_qn[(size_t)B_ * DM];
__device__ uint16_t g_qnhi[(size_t)B_ * DM];
__device__ uint16_t g_qnlo[(size_t)B_ * DM];
__device__ float    g_sn[FEW * DM];
__device__ float    g_h1[FEW * DI];
__device__ float    g_z[FEW * DM];
__device__ float    g_sg[FEW * DM];
__device__ float    g_sm[DM];
__device__ uint16_t g_Wghi[128 * 256];
__device__ uint16_t g_Wglo[128 * 256];
__device__ uint16_t g_WihNhi[1024 * 256];
__device__ uint16_t g_WihNlo[1024 * 256];
__device__ uint16_t g_WsNhi[1024 * XS];
__device__ uint16_t g_WsNlo[1024 * XS];
__device__ float    g_bias2[G1K];
__device__ float    g_A[(size_t)B_ * G1K];
__device__ float    g_G[(size_t)B_ * G1K];
__device__ uint16_t g_Xhi[(size_t)B_ * XS];
__device__ uint16_t g_Xlo[(size_t)B_ * XS];
__device__ float    g_c[(size_t)B_ * 256];

__device__ __forceinline__ float sigfast(float x) {
    return __fdividef(1.f, 1.f + __expf(-x));
}
__device__ __forceinline__ float tanhfast(float x) {
    float t = __expf(2.f * x);
    return 1.f - __fdividef(2.f, t + 1.f);
}
__device__ __forceinline__ uint32_t pack_bf16_hi(float x, float y,
                                                 uint32_t& lo_out) {
    __nv_bfloat16 hx = __float2bfloat16(x);
    __nv_bfloat16 hy = __float2bfloat16(y);
    float rx = x - __bfloat162float(hx);
    float ry = y - __bfloat162float(hy);
    __nv_bfloat16 lx = __float2bfloat16(rx);
    __nv_bfloat16 ly = __float2bfloat16(ry);
    uint32_t hi = (uint32_t)*(uint16_t*)&hx | ((uint32_t)*(uint16_t*)&hy << 16);
    lo_out = (uint32_t)*(uint16_t*)&lx | ((uint32_t)*(uint16_t*)&ly << 16);
    return hi;
}
__device__ __forceinline__ void pack1(float x, uint16_t& hi, uint16_t& lo) {
    __nv_bfloat16 h = __float2bfloat16(x);
    float r = x - __bfloat162float(h);
    __nv_bfloat16 l = __float2bfloat16(r);
    hi = *(uint16_t*)&h;
    lo = *(uint16_t*)&l;
}

// ---------------- mma.sync bf16x3 GEMM on pre-split operands ------------------
#define KC 32
#define SMS 40

__device__ __forceinline__ void mma16816(float* d, const uint32_t* a,
                                         const uint32_t* b) {
    asm volatile(
        "mma.sync.aligned.m16n8k16.row.col.f32.bf16.bf16.f32 "
        "{%0,%1,%2,%3}, {%4,%5,%6,%7}, {%8,%9}, {%0,%1,%2,%3};"
        : "+f"(d[0]), "+f"(d[1]), "+f"(d[2]), "+f"(d[3])
        : "r"(a[0]), "r"(a[1]), "r"(a[2]), "r"(a[3]), "r"(b[0]), "r"(b[1]));
}

__global__ __launch_bounds__(256, 2) void gemm_tc(
    const uint16_t* __restrict__ Ahi, const uint16_t* __restrict__ Alo,
    int lda, int M,
    const uint16_t* __restrict__ Bhi, const uint16_t* __restrict__ Blo,
    int ldb,
    float* __restrict__ C, int ldc,
    const float* __restrict__ Cadd, const float* __restrict__ bias, int NC) {
    __shared__ uint16_t sAh[128 * SMS];
    __shared__ uint16_t sAl[128 * SMS];
    __shared__ uint16_t sBh[128 * SMS];
    __shared__ uint16_t sBl[128 * SMS];

    const int t = threadIdx.x;
    const int w = t >> 5, lane = t & 31;
    const int g = lane >> 2, tig = lane & 3;
    const int m0 = blockIdx.x * 128, n0 = blockIdx.y * 128;
    const int mw = (w & 3) * 32;
    const int nw = (w >> 2) * 64;

    float acc[2][8][4];
#pragma unroll
    for (int mt = 0; mt < 2; mt++)
#pragma unroll
        for (int nt = 0; nt < 8; nt++)
#pragma unroll
            for (int e = 0; e < 4; e++) acc[mt][nt][e] = 0.f;

    const int lrow = t >> 1;
    const int lhalf = (t & 1) * 16;
    const bool mok = (m0 + lrow) < M;
    const size_t arow = (size_t)(m0 + lrow) * lda;
    const size_t brow = (size_t)(n0 + lrow) * ldb;
    const int sbase = lrow * SMS + lhalf;

    for (int c = 0; c < NC; c++) {
        const size_t ka = arow + c * KC + lhalf;
        const size_t kb_ = brow + c * KC + lhalf;
        __syncthreads();
        {
            uint4 z = make_uint4(0u, 0u, 0u, 0u);
            uint4 a0 = z, a1 = z, l0 = z, l1 = z;
            if (mok) {
                a0 = *(const uint4*)&Ahi[ka];
                a1 = *(const uint4*)&Ahi[ka + 8];
                l0 = *(const uint4*)&Alo[ka];
                l1 = *(const uint4*)&Alo[ka + 8];
            }
            *(uint4*)&sAh[sbase] = a0;
            *(uint4*)&sAh[sbase + 8] = a1;
            *(uint4*)&sAl[sbase] = l0;
            *(uint4*)&sAl[sbase + 8] = l1;
            uint4 b0 = *(const uint4*)&Bhi[kb_];
            uint4 b1 = *(const uint4*)&Bhi[kb_ + 8];
            uint4 c0 = *(const uint4*)&Blo[kb_];
            uint4 c1 = *(const uint4*)&Blo[kb_ + 8];
            *(uint4*)&sBh[sbase] = b0;
            *(uint4*)&sBh[sbase + 8] = b1;
            *(uint4*)&sBl[sbase] = c0;
            *(uint4*)&sBl[sbase + 8] = c1;
        }
        __syncthreads();

#pragma unroll
        for (int k16 = 0; k16 < 2; k16++) {
            const int kb = k16 * 16 + 2 * tig;
            uint32_t ah[2][4], al[2][4];
#pragma unroll
            for (int mt = 0; mt < 2; mt++) {
                int r0 = (mw + mt * 16 + g) * SMS;
                int r1 = r0 + 8 * SMS;
                ah[mt][0] = *(uint32_t*)&sAh[r0 + kb];
                ah[mt][1] = *(uint32_t*)&sAh[r1 + kb];
                ah[mt][2] = *(uint32_t*)&sAh[r0 + kb + 8];
                ah[mt][3] = *(uint32_t*)&sAh[r1 + kb + 8];
                al[mt][0] = *(uint32_t*)&sAl[r0 + kb];
                al[mt][1] = *(uint32_t*)&sAl[r1 + kb];
                al[mt][2] = *(uint32_t*)&sAl[r0 + kb + 8];
                al[mt][3] = *(uint32_t*)&sAl[r1 + kb + 8];
            }
#pragma unroll
            for (int nt = 0; nt < 8; nt++) {
                int rn = (nw + nt * 8 + g) * SMS;
                uint32_t bh[2], bl[2];
                bh[0] = *(uint32_t*)&sBh[rn + kb];
                bh[1] = *(uint32_t*)&sBh[rn + kb + 8];
                bl[0] = *(uint32_t*)&sBl[rn + kb];
                bl[1] = *(uint32_t*)&sBl[rn + kb + 8];
#pragma unroll
                for (int mt = 0; mt < 2; mt++) {
                    mma16816(acc[mt][nt], ah[mt], bh);
                    mma16816(acc[mt][nt], al[mt], bh);
                    mma16816(acc[mt][nt], ah[mt], bl);
                }
            }
        }
    }

#pragma unroll
    for (int mt = 0; mt < 2; mt++) {
        int mrow0 = m0 + mw + mt * 16 + g;
#pragma unroll
        for (int half = 0; half < 2; half++) {
            int m = mrow0 + half * 8;
            if (m >= M) continue;
            size_t cro = (size_t)m * ldc;
#pragma unroll
            for (int nt = 0; nt < 8; nt++) {
                int n = n0 + nw + nt * 8 + 2 * tig;
                float v0 = acc[mt][nt][half * 2];
                float v1 = acc[mt][nt][half * 2 + 1];
                if (bias) {
                    float2 bb = *(const float2*)&bias[n];
                    v0 += bb.x; v1 += bb.y;
                }
                if (Cadd) {
                    float2 ca = *(const float2*)&Cadd[cro + n];
                    v0 += ca.x; v1 += ca.y;
                }
                *(float2*)&C[cro + n] = make_float2(v0, v1);
            }
        }
    }
}

// ---------------- tiny prep kernels ------------------------------------------
__global__ void k_prep0(const float* __restrict__ gcn_w, const float* __restrict__ gcn_wb,
                        const float* __restrict__ gcn_b, const float* __restrict__ hop_gate,
                        const float* __restrict__ attn_w) {
    int t = threadIdx.x;  // 128
    if (t == 0) {
        float a = hop_gate[0], b = hop_gate[1];
        float m = fmaxf(a, b);
        float ea = expf(a - m), eb = expf(b - m);
        g_gw[0] = ea / (ea + eb);
        g_gw[1] = eb / (ea + eb);
    }
    if (t < 128) {
        g_biasvec[t] = gcn_wb[t] + gcn_b[t];
        float ur = 0.f, ue = 0.f;
        for (int d = 0; d < 128; d++) {
            float aw = attn_w[d];
            ur += gcn_w[d * 256 + t] * aw;
            ue += gcn_w[d * 256 + 128 + t] * aw;
        }
        g_u[t] = ur;
        g_u[128 + t] = ue;
    }
}

__global__ void k_prepG(const float* __restrict__ gcn_w) {
    int n = blockIdx.x;   // 128
    int t = threadIdx.x;  // 256
    uint16_t hi, lo;
    pack1(gcn_w[n * 256 + t], hi, lo);
    g_Wghi[n * 256 + t] = hi;
    g_Wglo[n * 256 + t] = lo;
}

__global__ void k_prepB(const float* __restrict__ w_ih, const float* __restrict__ w_hh,
                        const float* __restrict__ b_ih, const float* __restrict__ b_hh) {
    int n = blockIdx.x;   // 1024
    int t = threadIdx.x;  // 256
    int src = ((n >> 8) << 9) + (n & 255);
    uint16_t hi, lo;
    pack1(w_ih[src * 256 + t], hi, lo);
    g_WihNhi[n * 256 + t] = hi;
    g_WihNlo[n * 256 + t] = lo;
    pack1(w_hh[src * 512 + t], hi, lo);
    g_WsNhi[n * XS + t] = hi;
    g_WsNlo[n * XS + t] = lo;
    if (t < (XS - 261)) {
        g_WsNhi[n * XS + 261 + t] = 0;
        g_WsNlo[n * XS + 261 + t] = 0;
    }
    if (t == 0) g_bias2[n] = b_ih[src] + b_hh[src];
}

// ---------------- per-symbol score scalars + fp16 table ------------------------
__global__ __launch_bounds__(256) void k_scal(const float* __restrict__ emb) {
    __shared__ float su[256];
    int t = threadIdx.x;
    su[t] = g_u[t];
    __syncthreads();
    int warp = t >> 5, lane = t & 31;
    int s = blockIdx.x * 8 + warp;
    if (s >= NSYM) return;
    float4 e = *(const float4*)&emb[(size_t)s * 128 + lane * 4];
    float4 ur = ((const float4*)su)[lane];
    float4 ue = ((const float4*)(su + 128))[lane];
    float pr = e.x * ur.x + e.y * ur.y + e.z * ur.z + e.w * ur.w;
    float pe = e.x * ue.x + e.y * ue.y + e.z * ue.z + e.w * ue.w;
#pragma unroll
    for (int o = 16; o; o >>= 1) {
        pr += __shfl_xor_sync(0xffffffffu, pr, o);
        pe += __shfl_xor_sync(0xffffffffu, pe, o);
    }
    if (lane == 0) g_scal[s] = make_float2(pr, pe);
    __half2 h0 = __float22half2_rn(make_float2(e.x, e.y));
    __half2 h1 = __float22half2_rn(make_float2(e.z, e.w));
    uint2 pk;
    pk.x = *(uint32_t*)&h0;
    pk.y = *(uint32_t*)&h1;
    ((uint2*)g_embh)[(size_t)s * 32 + lane] = pk;
}

// ---------------- neighbor encoder: warp per (n, hop) --------------------------
__global__ __launch_bounds__(512) void k_neigh(
    const int* __restrict__ c0, const int* __restrict__ c1,
    const int* __restrict__ c2, const int* __restrict__ c3,
    int rowbase, int ncount) {
    __shared__ int4 smeta[16][64];
    const int t = threadIdx.x;
    const int w = t >> 5, lane = t & 31;
    const int g = w & 3;
    const int nb = blockIdx.x * 4 + (w >> 2);
    if (nb >= ncount) return;
    const int* cp = (g == 0) ? c0 : (g == 1) ? c1 : (g == 2) ? c2 : c3;

    int2 p0 = ((const int2*)cp)[(size_t)nb * NN_ + lane];
    int2 p1 = ((const int2*)cp)[(size_t)nb * NN_ + 32 + lane];
    float2 s0r = g_scal[p0.x], s0e = g_scal[p0.y];
    float2 s1r = g_scal[p1.x], s1e = g_scal[p1.y];
    float e0 = s0r.x + s0e.y;
    float e1 = s1r.x + s1e.y;
    float m = fmaxf(e0, e1);
#pragma unroll
    for (int o = 16; o; o >>= 1) m = fmaxf(m, __shfl_xor_sync(0xffffffffu, m, o));
    float w0 = __expf(e0 - m), w1 = __expf(e1 - m);
    float s = w0 + w1;
#pragma unroll
    for (int o = 16; o; o >>= 1) s += __shfl_xor_sync(0xffffffffu, s, o);
    float inv = __fdividef(1.f, s);

    smeta[w][lane]      = make_int4(p0.x, p0.y, __float_as_int(w0), 0);
    smeta[w][lane + 32] = make_int4(p1.x, p1.y, __float_as_int(w1), 0);
    __syncwarp();

    const uint2* e2 = (const uint2*)g_embh;
    float4 accR = make_float4(0.f, 0.f, 0.f, 0.f);
    float4 accE = make_float4(0.f, 0.f, 0.f, 0.f);
#pragma unroll 4
    for (int j = 0; j < NN_; j++) {
        int4 mt = smeta[w][j];
        float wj = __int_as_float(mt.z);
        uint2 vr = __ldg(&e2[(size_t)mt.x * 32 + lane]);
        uint2 ve = __ldg(&e2[(size_t)mt.y * 32 + lane]);
        float2 r01 = __half22float2(*(__half2*)&vr.x);
        float2 r23 = __half22float2(*(__half2*)&vr.y);
        float2 q01 = __half22float2(*(__half2*)&ve.x);
        float2 q23 = __half22float2(*(__half2*)&ve.y);
        accR.x += wj * r01.x; accR.y += wj * r01.y;
        accR.z += wj * r23.x; accR.w += wj * r23.y;
        accE.x += wj * q01.x; accE.y += wj * q01.y;
        accE.z += wj * q23.x; accE.w += wj * q23.y;
    }
    accR.x *= inv; accR.y *= inv; accR.z *= inv; accR.w *= inv;
    accE.x *= inv; accE.y *= inv; accE.z *= inv; accE.w *= inv;

    size_t yrow = (size_t)(rowbase + nb * 4 + g) * 256;
    uint32_t lo0, lo1;
    uint32_t hi0 = pack_bf16_hi(accR.x, accR.y, lo0);
    uint32_t hi1 = pack_bf16_hi(accR.z, accR.w, lo1);
    *(uint2*)&g_Yhi[yrow + 4 * lane] = make_uint2(hi0, hi1);
    *(uint2*)&g_Ylo[yrow + 4 * lane] = make_uint2(lo0, lo1);
    hi0 = pack_bf16_hi(accE.x, accE.y, lo0);
    hi1 = pack_bf16_hi(accE.z, accE.w, lo1);
    *(uint2*)&g_Yhi[yrow + 128 + 4 * lane] = make_uint2(hi0, hi1);
    *(uint2*)&g_Ylo[yrow + 128 + 4 * lane] = make_uint2(lo0, lo1);
}

// ---------------- combine: tanh + hop-gate mix ---------------------------------
__global__ void k_mix(float* __restrict__ out, uint16_t* __restrict__ outhi,
                      uint16_t* __restrict__ outlo, int rowbase) {
    int n = blockIdx.x, t = threadIdx.x;  // 256
    int side = t >> 7, d = t & 127;
    size_t r0 = (size_t)(rowbase + n * 4 + side * 2) * 128;
    float v = g_gw[0] * tanhfast(g_P[r0 + d]) + g_gw[1] * tanhfast(g_P[r0 + 128 + d]);
    out[(size_t)n * 256 + t] = v;
    if (outhi) {
        uint16_t hi, lo;
        pack1(v, hi, lo);
        outhi[(size_t)n * 256 + t] = hi;
        outlo[(size_t)n * 256 + t] = lo;
    }
}

// ---------------- support encoder chain ----------------------------------------
__device__ __forceinline__ float warp_sum(float v) {
#pragma unroll
    for (int o = 16; o; o >>= 1) v += __shfl_down_sync(0xffffffffu, v, o);
    return v;
}

__global__ void k_sup1(const float* __restrict__ p1_w, const float* __restrict__ p1_b) {
    int warp = threadIdx.x >> 5, lane = threadIdx.x & 31;
    int gw = blockIdx.x * 8 + warp;
    if (gw >= FEW * DI) return;
    int f = gw / DI, j = gw - f * DI;
    float s = 0.f;
#pragma unroll
    for (int i = 0; i < 8; i++) {
        int k = lane + i * 32;
        s += g_sn[f * DM + k] * p1_w[j * DM + k];
    }
    s = warp_sum(s);
    if (lane == 0) g_h1[f * DI + j] = fmaxf(s + p1_b[j], 0.f);
}

__global__ void k_sup2(const float* __restrict__ p2_w, const float* __restrict__ p2_b) {
    int warp = threadIdx.x >> 5, lane = threadIdx.x & 31;
    int gw = blockIdx.x * 8 + warp;
    if (gw >= FEW * DM) return;
    int f = gw / DM, d = gw - f * DM;
    float s = 0.f;
#pragma unroll
    for (int i = 0; i < 16; i++) {
        int k = lane + i * 32;
        s += g_h1[f * DI + k] * p2_w[d * DI + k];
    }
    s = warp_sum(s);
    if (lane == 0) g_z[f * DM + d] = s + p2_b[d] + g_sn[f * DM + d];
}

__global__ void k_lnmean(const float* __restrict__ ln_g, const float* __restrict__ ln_b) {
    __shared__ float sred[8];
    int t = threadIdx.x;
    int lane = t & 31, warp = t >> 5;
    float gg = ln_g[t], bb = ln_b[t];
    float msum = 0.f;
    for (int f = 0; f < FEW; f++) {
        float z = g_z[f * DM + t];
        float v = warp_sum(z);
        if (lane == 0) sred[warp] = v;
        __syncthreads();
        if (t == 0) {
            float s = 0.f;
            for (int w = 0; w < 8; w++) s += sred[w];
            sred[0] = s * (1.f / 256.f);
        }
        __syncthreads();
        float mu = sred[0];
        __syncthreads();
        float dv = z - mu;
        float v2 = warp_sum(dv * dv);
        if (lane == 0) sred[warp] = v2;
        __syncthreads();
        if (t == 0) {
            float s = 0.f;
            for (int w = 0; w < 8; w++) s += sred[w];
            sred[0] = s * (1.f / 256.f);
        }
        __syncthreads();
        float var = sred[0];
        __syncthreads();
        float o = dv * rsqrtf(var + 1e-6f) * gg + bb;
        g_sg[f * DM + t] = o;
        msum += o;
    }
    g_sm[t] = msum * (1.f / (float)FEW);
}

__global__ void k_sgw(const float* __restrict__ w_hh) {
    int warp = threadIdx.x >> 5, lane = threadIdx.x & 31;
    int gw = blockIdx.x * 8 + warp;
    if (gw >= FEW * G1K) return;
    int f = gw / G1K, n = gw - f * G1K;
    int src = ((n >> 8) << 9) + (n & 255);
    float s = 0.f;
#pragma unroll
    for (int i = 0; i < 8; i++) {
        int k = lane + i * 32;
        s += g_sg[f * DM + k] * w_hh[src * 512 + 256 + k];
    }
    s = warp_sum(s);
    if (lane == 0) {
        uint16_t hi, lo;
        pack1(s, hi, lo);
        g_WsNhi[n * XS + 256 + f] = hi;
        g_WsNlo[n * XS + 256 + f] = lo;
    }
}

// ---------------- fused LSTM cell + h update + attn softmax -------------------
__global__ __launch_bounds__(256) void k_lstm(const float* __restrict__ gates,
                                              int first, int last,
                                              float* __restrict__ out) {
    __shared__ float red[8][5];
    const int b = blockIdx.x, t = threadIdx.x;
    const float* gr = gates + (size_t)b * G1K;
    float gi = gr[t], gf = gr[256 + t], gg = gr[512 + t], go = gr[768 + t];
    float cold = first ? 0.f : g_c[(size_t)b * 256 + t];
    float cn = sigfast(gf) * cold + sigfast(gi) * tanhfast(gg);
    float hc = sigfast(go) * tanhfast(cn);
    g_c[(size_t)b * 256 + t] = cn;
    float hv = g_qn[(size_t)b * 256 + t] + hc;
    {
        uint16_t hi, lo;
        pack1(hv, hi, lo);
        g_Xhi[(size_t)b * XS + t] = hi;
        g_Xlo[(size_t)b * XS + t] = lo;
    }
    if (first && t < (XS - 261)) {
        g_Xhi[(size_t)b * XS + 261 + t] = 0;
        g_Xlo[(size_t)b * XS + 261 + t] = 0;
    }

    int lane = t & 31, warp = t >> 5;
    if (last) {
        float p = warp_sum(hv * g_sm[t]);
        if (lane == 0) red[warp][0] = p;
        __syncthreads();
        if (t == 0) {
            float s = 0.f;
            for (int w = 0; w < 8; w++) s += red[w][0];
            out[b] = s;
        }
    } else {
        float p[FEW];
#pragma unroll
        for (int f = 0; f < FEW; f++) p[f] = warp_sum(hv * g_sg[f * DM + t]);
        if (lane == 0)
#pragma unroll
            for (int f = 0; f < FEW; f++) red[warp][f] = p[f];
        __syncthreads();
        if (t == 0) {
            float s[FEW];
#pragma unroll
            for (int f = 0; f < FEW; f++) {
                float acc = 0.f;
                for (int w = 0; w < 8; w++) acc += red[w][f];
                s[f] = acc;
            }
            float m = s[0];
#pragma unroll
            for (int f = 1; f < FEW; f++) m = fmaxf(m, s[f]);
            float e[FEW], se = 0.f;
#pragma unroll
            for (int f = 0; f < FEW; f++) { e[f] = __expf(s[f] - m); se += e[f]; }
            float inv = __fdividef(1.f, se);
#pragma unroll
            for (int f = 0; f < FEW; f++) {
                uint16_t hi, lo;
                pack1(e[f] * inv, hi, lo);
                g_Xhi[(size_t)b * XS + 256 + f] = hi;
                g_Xlo[(size_t)b * XS + 256 + f] = lo;
            }
        }
    }
}

// ---------------- host launcher ------------------------------------------------
template <typename T>
static float* symaddrf(T& sym) {
    void* p = nullptr;
    cudaGetSymbolAddress(&p, sym);
    return (float*)p;
}
template <typename T>
static uint16_t* symaddru(T& sym) {
    void* p = nullptr;
    cudaGetSymbolAddress(&p, sym);
    return (uint16_t*)p;
}

extern "C" void kernel_launch(void* const* d_in, const int* in_sizes, int n_in,
                              void* d_out, int out_size) {
    const int* q_l1 = (const int*)d_in[0];
    const int* q_l2 = (const int*)d_in[1];
    const int* q_r1 = (const int*)d_in[2];
    const int* q_r2 = (const int*)d_in[3];
    const int* s_l1 = (const int*)d_in[4];
    const int* s_l2 = (const int*)d_in[5];
    const int* s_r1 = (const int*)d_in[6];
    const int* s_r2 = (const int*)d_in[7];
    const float* emb      = (const float*)d_in[12];
    const float* gcn_w    = (const float*)d_in[13];
    const float* gcn_wb   = (const float*)d_in[14];
    const float* gcn_b    = (const float*)d_in[15];
    const float* hop_gate = (const float*)d_in[16];
    const float* attn_w   = (const float*)d_in[17];
    const float* p1_w = (const float*)d_in[19];
    const float* p1_b = (const float*)d_in[20];
    const float* p2_w = (const float*)d_in[21];
    const float* p2_b = (const float*)d_in[22];
    const float* ln_g = (const float*)d_in[23];
    const float* ln_b = (const float*)d_in[24];
    const float* w_ih = (const float*)d_in[25];
    const float* w_hh = (const float*)d_in[26];
    const float* b_ih = (const float*)d_in[27];
    const float* b_hh = (const float*)d_in[28];
    float* out = (float*)d_out;

    uint16_t* pYhi  = symaddru(g_Yhi);
    uint16_t* pYlo  = symaddru(g_Ylo);
    uint16_t* pWghi = symaddru(g_Wghi);
    uint16_t* pWglo = symaddru(g_Wglo);
    uint16_t* pWihhi = symaddru(g_WihNhi);
    uint16_t* pWihlo = symaddru(g_WihNlo);
    uint16_t* pWshi = symaddru(g_WsNhi);
    uint16_t* pWslo = symaddru(g_WsNlo);
    uint16_t* pQhi  = symaddru(g_qnhi);
    uint16_t* pQlo  = symaddru(g_qnlo);
    uint16_t* pXhi  = symaddru(g_Xhi);
    uint16_t* pXlo  = symaddru(g_Xlo);
    float* pP     = symaddrf(g_P);
    float* pQn    = symaddrf(g_qn);
    float* pSn    = symaddrf(g_sn);
    float* pBias2 = symaddrf(g_bias2);
    float* pBiasV = symaddrf(g_biasvec);
    float* pA     = symaddrf(g_A);
    float* pG     = symaddrf(g_G);

    // prep
    k_prep0<<<1, 128>>>(gcn_w, gcn_wb, gcn_b, hop_gate, attn_w);
    k_prepG<<<128, 256>>>(gcn_w);
    k_prepB<<<1024, 256>>>(w_ih, w_hh, b_ih, b_hh);
    k_scal<<<(NSYM + 7) / 8, 256>>>(emb);

    // neighbor encoders: weighted fp16-embedding sums -> Y (bf16 hi/lo)
    k_neigh<<<B_ / 4, 512>>>(q_l1, q_l2, q_r1, q_r2, 0, B_);
    k_neigh<<<(FEW + 3) / 4, 512>>>(s_l1, s_l2, s_r1, s_r2, B_ * 4, FEW);

    // P = Y @ gcn_w^T + biasvec   [16404,256]@[256,128]
    gemm_tc<<<dim3((YROWS + 127) / 128, 1), 256>>>(
        pYhi, pYlo, 256, YROWS, pWghi, pWglo, 256, pP, 128, nullptr, pBiasV, 8);

    // tanh + hop-gate mix
    k_mix<<<B_, 256>>>(pQn, pQhi, pQlo, 0);
    k_mix<<<FEW, 256>>>(pSn, nullptr, nullptr, B_ * 4);

    // support encoder
    k_sup1<<<(FEW * DI) / 8, 256>>>(p1_w, p1_b);
    k_sup2<<<(FEW * DM) / 8, 256>>>(p2_w, p2_b);
    k_lnmean<<<1, 256>>>(ln_g, ln_b);
    k_sgw<<<(FEW * G1K + 7) / 8, 256>>>(w_hh);

    // A = qn @ w_ihN^T + (b_ih + b_hh)   [4096,256]@[256,1024]
    gemm_tc<<<dim3(B_ / 128, G1K / 128), 256>>>(
        pQhi, pQlo, 256, B_, pWihhi, pWihlo, 256, pA, G1K, nullptr, pBias2, 8);

    // step 1: gates = A (h_r = 0)
    k_lstm<<<B_, 256>>>(pA, 1, 0, out);

    // steps 2..4: G = A + [h|attn|0] @ WstepN^T   [4096,288]@[288,1024]
    for (int s = 2; s <= 4; s++) {
        gemm_tc<<<dim3(B_ / 128, G1K / 128), 256>>>(
            pXhi, pXlo, XS, B_, pWshi, pWslo, XS, pG, G1K, pA, nullptr, 9);
        k_lstm<<<B_, 256>>>(pG, 0, (s == 4) ? 1 : 0, out);
    }
}